// round 1
// baseline (speedup 1.0000x reference)
#include <cuda_runtime.h>
#include <math.h>

#define BB   4
#define NTOK 4096
#define CC   256
#define DD   32

// Scratch (allocation-free per harness rules)
__device__ float g_q[BB * NTOK * DD];
__device__ float g_k[BB * NTOK * DD];
__device__ float g_v[BB * NTOK * CC];
__device__ float g_att[BB * NTOK * CC];

// ---------------------------------------------------------------------------
// Tiled GEMM: Y[M,N] = X[M,K] @ W[K,N] + bias  (+ optional residual add)
// Block tile 64x64, 256 threads, 4x4 micro-tile per thread, K-chunks of 32.
// ---------------------------------------------------------------------------
template <bool RESID>
__global__ __launch_bounds__(256) void gemm_kernel(
    const float* __restrict__ X, const float* __restrict__ W,
    const float* __restrict__ bias, const float* __restrict__ resid,
    float* __restrict__ Y, int M, int K, int N)
{
    __shared__ float sX[64][33];
    __shared__ float sW[32][68];

    const int tid = threadIdx.x;
    const int tx = tid & 15;       // 0..15 -> 4 output cols each
    const int ty = tid >> 4;       // 0..15 -> 4 output rows each
    const int row0 = blockIdx.y * 64;
    const int col0 = blockIdx.x * 64;

    float acc[4][4] = {};

    for (int kt = 0; kt < K; kt += 32) {
        // load X tile [64 x 32]
        #pragma unroll
        for (int i = 0; i < 8; i++) {
            int idx = tid + i * 256;
            int r = idx >> 5, c = idx & 31;
            sX[r][c] = X[(size_t)(row0 + r) * K + kt + c];
        }
        // load W tile [32 x 64] (guarded for N < 64)
        #pragma unroll
        for (int i = 0; i < 8; i++) {
            int idx = tid + i * 256;
            int r = idx >> 6, c = idx & 63;
            int col = col0 + c;
            sW[r][c] = (col < N) ? W[(size_t)(kt + r) * N + col] : 0.0f;
        }
        __syncthreads();

        #pragma unroll
        for (int kk = 0; kk < 32; kk++) {
            float a0 = sX[ty * 4 + 0][kk];
            float a1 = sX[ty * 4 + 1][kk];
            float a2 = sX[ty * 4 + 2][kk];
            float a3 = sX[ty * 4 + 3][kk];
            float4 b = *(const float4*)&sW[kk][tx * 4];
            acc[0][0] += a0 * b.x; acc[0][1] += a0 * b.y; acc[0][2] += a0 * b.z; acc[0][3] += a0 * b.w;
            acc[1][0] += a1 * b.x; acc[1][1] += a1 * b.y; acc[1][2] += a1 * b.z; acc[1][3] += a1 * b.w;
            acc[2][0] += a2 * b.x; acc[2][1] += a2 * b.y; acc[2][2] += a2 * b.z; acc[2][3] += a2 * b.w;
            acc[3][0] += a3 * b.x; acc[3][1] += a3 * b.y; acc[3][2] += a3 * b.z; acc[3][3] += a3 * b.w;
        }
        __syncthreads();
    }

    #pragma unroll
    for (int i = 0; i < 4; i++) {
        int row = row0 + ty * 4 + i;
        #pragma unroll
        for (int j = 0; j < 4; j++) {
            int col = col0 + tx * 4 + j;
            if (col < N) {
                float v = acc[i][j] + bias[col];
                if (RESID) v += resid[(size_t)row * N + col];
                Y[(size_t)row * N + col] = v;
            }
        }
    }
}

// ---------------------------------------------------------------------------
// Flash attention (fp32): per block, 64 query rows of one batch.
// 8 warps; warp w owns query rows [w*8, w*8+8). Each lane holds an
// acc[8 rows][8 cols] micro-tile (cols = lane + 32*ci).
// K tiles of 64 keys; online softmax; P staged in smem per-warp.
// ---------------------------------------------------------------------------
__global__ __launch_bounds__(256) void attn_kernel(
    const float* __restrict__ gq, const float* __restrict__ gk,
    const float* __restrict__ gv, float* __restrict__ gatt)
{
    extern __shared__ float sm[];
    float* sQ = sm;                    // 64 * 33
    float* sK = sQ + 64 * 33;          // 64 * 33
    float* sP = sK + 64 * 33;          // 64 * 64
    float* sV = sP + 64 * 64;          // 64 * 256

    const int tid  = threadIdx.x;
    const int lane = tid & 31;
    const int warp = tid >> 5;
    const int r0   = warp * 8;

    const int b  = blockIdx.y;
    const int qt = blockIdx.x;

    const float* qb = gq + (size_t)b * NTOK * DD + (size_t)qt * 64 * DD;
    const float* kb = gk + (size_t)b * NTOK * DD;
    const float* vb = gv + (size_t)b * NTOK * CC;

    // load Q tile, pre-scaled by 1/sqrt(D)
    const float qscale = 0.17677669529663689f;
    #pragma unroll
    for (int i = 0; i < 8; i++) {
        int idx = tid + i * 256;
        int r = idx >> 5, c = idx & 31;
        sQ[r * 33 + c] = qb[r * DD + c] * qscale;
    }

    float acc[8][8];
    #pragma unroll
    for (int ri = 0; ri < 8; ri++)
        #pragma unroll
        for (int ci = 0; ci < 8; ci++) acc[ri][ci] = 0.0f;

    float mrow[8], lrow[8];
    #pragma unroll
    for (int ri = 0; ri < 8; ri++) { mrow[ri] = -1e30f; lrow[ri] = 0.0f; }

    for (int kt = 0; kt < NTOK / 64; kt++) {
        __syncthreads();  // protect sK/sV (and orders sQ writes on first iter)

        // load K tile [64 x 32]
        #pragma unroll
        for (int i = 0; i < 8; i++) {
            int idx = tid + i * 256;
            int r = idx >> 5, c = idx & 31;
            sK[r * 33 + c] = kb[(size_t)(kt * 64 + r) * DD + c];
        }
        // load V tile [64 x 256] as float4
        {
            const float4* vsrc = (const float4*)(vb + (size_t)kt * 64 * CC);
            float4* vdst = (float4*)sV;
            #pragma unroll
            for (int i = 0; i < 16; i++) vdst[tid + i * 256] = vsrc[tid + i * 256];
        }
        __syncthreads();

        // scores: lane covers key cols {lane, lane+32} for its warp's 8 rows
        float s0[8], s1[8];
        #pragma unroll
        for (int ri = 0; ri < 8; ri++) { s0[ri] = 0.0f; s1[ri] = 0.0f; }

        #pragma unroll
        for (int dc = 0; dc < 32; dc += 8) {
            float k0[8], k1[8];
            #pragma unroll
            for (int dd = 0; dd < 8; dd++) {
                k0[dd] = sK[lane * 33 + dc + dd];
                k1[dd] = sK[(lane + 32) * 33 + dc + dd];
            }
            #pragma unroll
            for (int ri = 0; ri < 8; ri++) {
                #pragma unroll
                for (int dd = 0; dd < 8; dd++) {
                    float qv = sQ[(r0 + ri) * 33 + dc + dd];
                    s0[ri] += qv * k0[dd];
                    s1[ri] += qv * k1[dd];
                }
            }
        }

        // online softmax update + stage P
        #pragma unroll
        for (int ri = 0; ri < 8; ri++) {
            float tmax = fmaxf(s0[ri], s1[ri]);
            #pragma unroll
            for (int off = 16; off > 0; off >>= 1)
                tmax = fmaxf(tmax, __shfl_xor_sync(0xFFFFFFFFu, tmax, off));
            float mnew = fmaxf(mrow[ri], tmax);
            float p0 = __expf(s0[ri] - mnew);
            float p1 = __expf(s1[ri] - mnew);
            float psum = p0 + p1;
            #pragma unroll
            for (int off = 16; off > 0; off >>= 1)
                psum += __shfl_xor_sync(0xFFFFFFFFu, psum, off);
            float corr = __expf(mrow[ri] - mnew);
            lrow[ri] = lrow[ri] * corr + psum;
            mrow[ri] = mnew;
            #pragma unroll
            for (int ci = 0; ci < 8; ci++) acc[ri][ci] *= corr;
            sP[(r0 + ri) * 64 + lane]      = p0;
            sP[(r0 + ri) * 64 + lane + 32] = p1;
        }
        // no block sync needed: each warp reads only its own sP rows

        // PV accumulate
        #pragma unroll 4
        for (int j = 0; j < 64; j++) {
            float vv[8];
            #pragma unroll
            for (int ci = 0; ci < 8; ci++) vv[ci] = sV[j * CC + lane + 32 * ci];
            #pragma unroll
            for (int ri = 0; ri < 8; ri++) {
                float p = sP[(r0 + ri) * 64 + j];
                #pragma unroll
                for (int ci = 0; ci < 8; ci++) acc[ri][ci] += p * vv[ci];
            }
        }
    }

    // epilogue: normalize and store
    float* ob = gatt + (size_t)b * NTOK * CC + (size_t)qt * 64 * CC;
    #pragma unroll
    for (int ri = 0; ri < 8; ri++) {
        float inv = 1.0f / lrow[ri];
        #pragma unroll
        for (int ci = 0; ci < 8; ci++)
            ob[(size_t)(r0 + ri) * CC + lane + 32 * ci] = acc[ri][ci] * inv;
    }
}

// ---------------------------------------------------------------------------
extern "C" void kernel_launch(void* const* d_in, const int* in_sizes, int n_in,
                              void* d_out, int out_size)
{
    const float* x  = (const float*)d_in[0];
    const float* wq = (const float*)d_in[1];
    const float* bq = (const float*)d_in[2];
    const float* wk = (const float*)d_in[3];
    const float* bk = (const float*)d_in[4];
    const float* wv = (const float*)d_in[5];
    const float* bv = (const float*)d_in[6];
    const float* wo = (const float*)d_in[7];
    const float* bo = (const float*)d_in[8];
    float* out = (float*)d_out;

    float *q, *k, *v, *att;
    cudaGetSymbolAddress((void**)&q,   g_q);
    cudaGetSymbolAddress((void**)&k,   g_k);
    cudaGetSymbolAddress((void**)&v,   g_v);
    cudaGetSymbolAddress((void**)&att, g_att);

    const int M = BB * NTOK;  // 16384
    dim3 blk(256);

    // Q, K, V projections
    gemm_kernel<false><<<dim3(1, M / 64), blk>>>(x, wq, bq, nullptr, q, M, CC, DD);
    gemm_kernel<false><<<dim3(1, M / 64), blk>>>(x, wk, bk, nullptr, k, M, CC, DD);
    gemm_kernel<false><<<dim3(4, M / 64), blk>>>(x, wv, bv, nullptr, v, M, CC, CC);

    // attention
    size_t smem = (size_t)(64 * 33 * 2 + 64 * 64 + 64 * 256) * sizeof(float);  // 98816 B
    cudaFuncSetAttribute(attn_kernel, cudaFuncAttributeMaxDynamicSharedMemorySize, (int)smem);
    attn_kernel<<<dim3(NTOK / 64, BB), blk, smem>>>(q, k, v, att);

    // output projection + bias + residual
    gemm_kernel<true><<<dim3(4, M / 64), blk>>>(att, wo, bo, x, out, M, CC, CC);
}

// round 2
// speedup vs baseline: 2.7976x; 2.7976x over previous
#include <cuda_runtime.h>
#include <cuda_bf16.h>
#include <math.h>
#include <stdint.h>

#define BB   4
#define NTOK 4096
#define CC   256
#define DD   32

// Scratch (allocation-free per harness rules)
__device__ __nv_bfloat16 g_q[BB * NTOK * DD];
__device__ __nv_bfloat16 g_k[BB * NTOK * DD];
__device__ __nv_bfloat16 g_v[BB * NTOK * CC];
__device__ float         g_att[BB * NTOK * CC];

// ---------------------------------------------------------------------------
// PTX helpers
// ---------------------------------------------------------------------------
__device__ __forceinline__ uint32_t smem_u32(const void* p) {
    return (uint32_t)__cvta_generic_to_shared(p);
}
__device__ __forceinline__ void ldsm_x4(uint32_t& r0, uint32_t& r1, uint32_t& r2, uint32_t& r3, uint32_t addr) {
    asm volatile("ldmatrix.sync.aligned.m8n8.x4.shared.b16 {%0,%1,%2,%3}, [%4];\n"
                 : "=r"(r0), "=r"(r1), "=r"(r2), "=r"(r3) : "r"(addr));
}
__device__ __forceinline__ void ldsm_x2(uint32_t& r0, uint32_t& r1, uint32_t addr) {
    asm volatile("ldmatrix.sync.aligned.m8n8.x2.shared.b16 {%0,%1}, [%2];\n"
                 : "=r"(r0), "=r"(r1) : "r"(addr));
}
__device__ __forceinline__ void ldsm_x2_trans(uint32_t& r0, uint32_t& r1, uint32_t addr) {
    asm volatile("ldmatrix.sync.aligned.m8n8.x2.trans.shared.b16 {%0,%1}, [%2];\n"
                 : "=r"(r0), "=r"(r1) : "r"(addr));
}
__device__ __forceinline__ void mma_bf16(float* c, uint32_t a0, uint32_t a1, uint32_t a2, uint32_t a3,
                                         uint32_t b0, uint32_t b1) {
    asm volatile(
        "mma.sync.aligned.m16n8k16.row.col.f32.bf16.bf16.f32 "
        "{%0,%1,%2,%3}, {%4,%5,%6,%7}, {%8,%9}, {%0,%1,%2,%3};\n"
        : "+f"(c[0]), "+f"(c[1]), "+f"(c[2]), "+f"(c[3])
        : "r"(a0), "r"(a1), "r"(a2), "r"(a3), "r"(b0), "r"(b1));
}
__device__ __forceinline__ void cp_async16(uint32_t smem_dst, const void* gsrc) {
    asm volatile("cp.async.cg.shared.global [%0], [%1], 16;\n" :: "r"(smem_dst), "l"(gsrc));
}
__device__ __forceinline__ void cp_async_commit() { asm volatile("cp.async.commit_group;\n"); }
__device__ __forceinline__ void cp_async_wait0()  { asm volatile("cp.async.wait_group 0;\n"); }

// FFMA-only exp2 (MUFU.EX2 rt is 8 cyc/SMSP -> would be the bottleneck).
// Valid for x in ~[-100, 30]; here x in ~[-60, 15]. Rel err ~4e-5.
__device__ __forceinline__ float exp2_fast(float x) {
    float fr = x + 12582912.0f;           // 1.5 * 2^23: low mantissa bits = round(x)
    int   n  = __float_as_int(fr);
    float f  = x - (fr - 12582912.0f);    // f in [-0.5, 0.5]
    float p  = 0.0096181291f;
    p = fmaf(p, f, 0.0555041087f);
    p = fmaf(p, f, 0.2402265070f);
    p = fmaf(p, f, 0.6931471806f);
    p = fmaf(p, f, 1.0f);
    return __int_as_float(__float_as_int(p) + (n << 23));
}
__device__ __forceinline__ uint32_t pack_bf16(float lo, float hi) {
    __nv_bfloat162 h = __floats2bfloat162_rn(lo, hi);   // .x = lo (low half)
    return *reinterpret_cast<uint32_t*>(&h);
}

// ---------------------------------------------------------------------------
// Tiled fp32 GEMM: Y[M,N] = X[M,K] @ W[K,N] + bias  (+resid). Output fp32 or
// scaled bf16 (used to feed the bf16 tensor-core attention).
// ---------------------------------------------------------------------------
template <bool RESID, bool BF16OUT>
__global__ __launch_bounds__(256) void gemm_kernel(
    const float* __restrict__ X, const float* __restrict__ W,
    const float* __restrict__ bias, const float* __restrict__ resid,
    void* __restrict__ Yv, int M, int K, int N, float oscale)
{
    __shared__ float sX[64][33];
    __shared__ float sW[32][68];

    const int tid = threadIdx.x;
    const int tx = tid & 15;
    const int ty = tid >> 4;
    const int row0 = blockIdx.y * 64;
    const int col0 = blockIdx.x * 64;

    float acc[4][4] = {};

    for (int kt = 0; kt < K; kt += 32) {
        #pragma unroll
        for (int i = 0; i < 8; i++) {
            int idx = tid + i * 256;
            int r = idx >> 5, c = idx & 31;
            sX[r][c] = X[(size_t)(row0 + r) * K + kt + c];
        }
        #pragma unroll
        for (int i = 0; i < 8; i++) {
            int idx = tid + i * 256;
            int r = idx >> 6, c = idx & 63;
            int col = col0 + c;
            sW[r][c] = (col < N) ? W[(size_t)(kt + r) * N + col] : 0.0f;
        }
        __syncthreads();

        #pragma unroll
        for (int kk = 0; kk < 32; kk++) {
            float a0 = sX[ty * 4 + 0][kk];
            float a1 = sX[ty * 4 + 1][kk];
            float a2 = sX[ty * 4 + 2][kk];
            float a3 = sX[ty * 4 + 3][kk];
            float4 b = *(const float4*)&sW[kk][tx * 4];
            acc[0][0] += a0 * b.x; acc[0][1] += a0 * b.y; acc[0][2] += a0 * b.z; acc[0][3] += a0 * b.w;
            acc[1][0] += a1 * b.x; acc[1][1] += a1 * b.y; acc[1][2] += a1 * b.z; acc[1][3] += a1 * b.w;
            acc[2][0] += a2 * b.x; acc[2][1] += a2 * b.y; acc[2][2] += a2 * b.z; acc[2][3] += a2 * b.w;
            acc[3][0] += a3 * b.x; acc[3][1] += a3 * b.y; acc[3][2] += a3 * b.z; acc[3][3] += a3 * b.w;
        }
        __syncthreads();
    }

    #pragma unroll
    for (int i = 0; i < 4; i++) {
        int row = row0 + ty * 4 + i;
        #pragma unroll
        for (int j = 0; j < 4; j++) {
            int col = col0 + tx * 4 + j;
            if (col < N) {
                float v = acc[i][j] + bias[col];
                if (RESID) v += resid[(size_t)row * N + col];
                if (BF16OUT)
                    ((__nv_bfloat16*)Yv)[(size_t)row * N + col] = __float2bfloat16(v * oscale);
                else
                    ((float*)Yv)[(size_t)row * N + col] = v;
            }
        }
    }
}

// ---------------------------------------------------------------------------
// Flash attention, bf16 tensor-core (mma.sync m16n8k16), no online max
// (scores bounded; fixed max = 0), FFMA exp2, cp.async double-buffered K/V.
//
// CTA: 64 query rows of one batch, 8 warps = 4 (M blocks of 16) x 2 (V-col
// halves of 128). Warps in a (wm, *) pair both compute the full 16x64 S tile
// (S is 1/8th of the PV flops; duplication beats a cross-warp P exchange).
// ---------------------------------------------------------------------------
#define KSTRIDE 40   // bf16 elems per row (32 + 8 pad) -> 80 B
#define VSTRIDE 264  // bf16 elems per row (256 + 8 pad) -> 528 B
#define KBYTES  (64 * KSTRIDE * 2)   // 5120
#define VBYTES  (64 * VSTRIDE * 2)   // 33792

__global__ __launch_bounds__(256) void attn_kernel(
    const __nv_bfloat16* __restrict__ gq, const __nv_bfloat16* __restrict__ gk,
    const __nv_bfloat16* __restrict__ gv, float* __restrict__ gatt)
{
    extern __shared__ char smraw[];
    char* sQ = smraw;                      // 64 x KSTRIDE bf16
    char* sK0 = sQ + KBYTES;
    char* sV0 = sK0 + KBYTES;
    char* sK1 = sV0 + VBYTES;
    char* sV1 = sK1 + KBYTES;

    const int tid  = threadIdx.x;
    const int lane = tid & 31;
    const int warp = tid >> 5;
    const int wm   = warp >> 1;            // 0..3 -> rows 16*wm
    const int wn   = warp & 1;             // 0..1 -> V cols 128*wn

    const int b  = blockIdx.y;
    const int qt = blockIdx.x;

    const __nv_bfloat16* qb = gq + (size_t)b * NTOK * DD + (size_t)qt * 64 * DD;
    const __nv_bfloat16* kb = gk + (size_t)b * NTOK * DD;
    const __nv_bfloat16* vb = gv + (size_t)b * NTOK * CC;

    const uint32_t sQ_u = smem_u32(sQ);
    const uint32_t sK_u[2] = { smem_u32(sK0), smem_u32(sK1) };
    const uint32_t sV_u[2] = { smem_u32(sV0), smem_u32(sV1) };

    // ---- stage Q (64x32 bf16, contiguous 4 KB) ----
    {
        int r = tid >> 2, c8 = tid & 3;                 // 8 bf16 per thread
        const uint4* src = (const uint4*)(qb + (size_t)r * DD + c8 * 8);
        *(uint4*)(sQ + r * (KSTRIDE * 2) + c8 * 16) = *src;
    }

    // ---- prologue: async load K/V tile 0 ----
    {
        // K: 64x32 bf16 contiguous (4 KB) = 256 x 16B
        int r = tid >> 2, c = tid & 3;
        cp_async16(sK_u[0] + r * (KSTRIDE * 2) + c * 16, kb + (size_t)r * DD + c * 8);
        // V: 64x256 bf16 contiguous (32 KB) = 2048 x 16B, 8 per thread
        #pragma unroll
        for (int i = 0; i < 8; i++) {
            int idx = tid + i * 256;
            int vr = idx >> 5, vc = idx & 31;
            cp_async16(sV_u[0] + vr * (VSTRIDE * 2) + vc * 16, vb + (size_t)vr * CC + vc * 8);
        }
    }
    cp_async_commit();
    __syncthreads();   // Q staged

    // ---- Q fragments (resident for whole kernel) ----
    uint32_t qA[2][4];
    {
        int lrow = lane & 15;
        int lcolh = (lane >> 4) << 3;      // 0 or 8 (bf16 elems)
        uint32_t base = sQ_u + (16 * wm + lrow) * (KSTRIDE * 2) + lcolh * 2;
        ldsm_x4(qA[0][0], qA[0][1], qA[0][2], qA[0][3], base);
        ldsm_x4(qA[1][0], qA[1][1], qA[1][2], qA[1][3], base + 32);
    }

    float acc[16][4];
    #pragma unroll
    for (int j = 0; j < 16; j++)
        #pragma unroll
        for (int q4 = 0; q4 < 4; q4++) acc[j][q4] = 0.0f;
    float lsum0 = 0.0f, lsum1 = 0.0f;

    const int krow = lane & 7;
    const int khalf16 = ((lane & 15) >> 3) * 16;  // byte offset for 2nd k-matrix
    const int vrow = (lane & 7) + ((lane & 15) >> 3) * 8;

    for (int kt = 0; kt < NTOK / 64; kt++) {
        cp_async_wait0();
        __syncthreads();   // tile kt ready everywhere; prev compute done

        if (kt + 1 < NTOK / 64) {
            int nb = (kt + 1) & 1;
            const __nv_bfloat16* kbt = kb + (size_t)(kt + 1) * 64 * DD;
            const __nv_bfloat16* vbt = vb + (size_t)(kt + 1) * 64 * CC;
            int r = tid >> 2, c = tid & 3;
            cp_async16(sK_u[nb] + r * (KSTRIDE * 2) + c * 16, kbt + (size_t)r * DD + c * 8);
            #pragma unroll
            for (int i = 0; i < 8; i++) {
                int idx = tid + i * 256;
                int vr = idx >> 5, vc = idx & 31;
                cp_async16(sV_u[nb] + vr * (VSTRIDE * 2) + vc * 16, vbt + (size_t)vr * CC + vc * 8);
            }
        }
        cp_async_commit();

        const uint32_t sKb = sK_u[kt & 1];
        const uint32_t sVb = sV_u[kt & 1];

        // ---- S = Q @ K^T (16 rows x 64 keys per warp, fp32 accum) ----
        float sfrag[8][4];
        #pragma unroll
        for (int nt = 0; nt < 8; nt++)
            #pragma unroll
            for (int q4 = 0; q4 < 4; q4++) sfrag[nt][q4] = 0.0f;

        #pragma unroll
        for (int kbk = 0; kbk < 2; kbk++) {
            #pragma unroll
            for (int nt = 0; nt < 8; nt++) {
                uint32_t b0, b1;
                uint32_t addr = sKb + (nt * 8 + krow) * (KSTRIDE * 2) + kbk * 32 + khalf16;
                ldsm_x2(b0, b1, addr);
                mma_bf16(sfrag[nt], qA[kbk][0], qA[kbk][1], qA[kbk][2], qA[kbk][3], b0, b1);
            }
        }

        // ---- P = exp2(S) (Q pre-scaled by log2e/sqrt(D)); pack to bf16 ----
        uint32_t plo[8], phi[8];
        #pragma unroll
        for (int nt = 0; nt < 8; nt++) {
            float p0 = exp2_fast(sfrag[nt][0]);
            float p1 = exp2_fast(sfrag[nt][1]);
            float p2 = exp2_fast(sfrag[nt][2]);
            float p3 = exp2_fast(sfrag[nt][3]);
            lsum0 += p0 + p1;
            lsum1 += p2 + p3;
            plo[nt] = pack_bf16(p0, p1);
            phi[nt] = pack_bf16(p2, p3);
        }

        // ---- O += P @ V (16 rows x 128 cols per warp) ----
        #pragma unroll
        for (int kb2 = 0; kb2 < 4; kb2++) {
            uint32_t a0 = plo[2 * kb2], a1 = phi[2 * kb2];
            uint32_t a2 = plo[2 * kb2 + 1], a3 = phi[2 * kb2 + 1];
            #pragma unroll
            for (int j = 0; j < 16; j++) {
                uint32_t b0, b1;
                uint32_t addr = sVb + (kb2 * 16 + vrow) * (VSTRIDE * 2) + wn * 256 + j * 16;
                ldsm_x2_trans(b0, b1, addr);
                mma_bf16(acc[j], a0, a1, a2, a3, b0, b1);
            }
        }
    }

    // ---- epilogue: row sums (duplicated S => full sums per warp), divide ----
    lsum0 += __shfl_xor_sync(0xFFFFFFFFu, lsum0, 1);
    lsum0 += __shfl_xor_sync(0xFFFFFFFFu, lsum0, 2);
    lsum1 += __shfl_xor_sync(0xFFFFFFFFu, lsum1, 1);
    lsum1 += __shfl_xor_sync(0xFFFFFFFFu, lsum1, 2);
    float inv0 = 1.0f / lsum0;
    float inv1 = 1.0f / lsum1;

    float* ob = gatt + (size_t)b * NTOK * CC + (size_t)qt * 64 * CC;
    int row0 = 16 * wm + (lane >> 2);
    int colb = wn * 128 + (lane & 3) * 2;
    #pragma unroll
    for (int j = 0; j < 16; j++) {
        int col = colb + j * 8;
        *(float2*)&ob[(size_t)row0 * CC + col]       = make_float2(acc[j][0] * inv0, acc[j][1] * inv0);
        *(float2*)&ob[(size_t)(row0 + 8) * CC + col] = make_float2(acc[j][2] * inv1, acc[j][3] * inv1);
    }
}

// ---------------------------------------------------------------------------
extern "C" void kernel_launch(void* const* d_in, const int* in_sizes, int n_in,
                              void* d_out, int out_size)
{
    const float* x  = (const float*)d_in[0];
    const float* wq = (const float*)d_in[1];
    const float* bq = (const float*)d_in[2];
    const float* wk = (const float*)d_in[3];
    const float* bk = (const float*)d_in[4];
    const float* wv = (const float*)d_in[5];
    const float* bv = (const float*)d_in[6];
    const float* wo = (const float*)d_in[7];
    const float* bo = (const float*)d_in[8];
    float* out = (float*)d_out;

    __nv_bfloat16 *q, *k, *v;
    float* att;
    cudaGetSymbolAddress((void**)&q,   g_q);
    cudaGetSymbolAddress((void**)&k,   g_k);
    cudaGetSymbolAddress((void**)&v,   g_v);
    cudaGetSymbolAddress((void**)&att, g_att);

    const int M = BB * NTOK;  // 16384
    dim3 blk(256);

    // fold 1/sqrt(D) and log2(e) into Q so softmax is exp2(S)
    const float qscale = 1.4426950408889634f / 5.656854249492380f;

    gemm_kernel<false, true><<<dim3(1, M / 64), blk>>>(x, wq, bq, nullptr, q, M, CC, DD, qscale);
    gemm_kernel<false, true><<<dim3(1, M / 64), blk>>>(x, wk, bk, nullptr, k, M, CC, DD, 1.0f);
    gemm_kernel<false, true><<<dim3(4, M / 64), blk>>>(x, wv, bv, nullptr, v, M, CC, CC, 1.0f);

    size_t smem = KBYTES + 2 * (KBYTES + VBYTES);   // 82944 B
    cudaFuncSetAttribute(attn_kernel, cudaFuncAttributeMaxDynamicSharedMemorySize, (int)smem);
    attn_kernel<<<dim3(NTOK / 64, BB), blk, smem>>>(q, k, v, att);

    gemm_kernel<true, false><<<dim3(4, M / 64), blk>>>(att, wo, bo, x, out, M, CC, CC, 1.0f);
}

// round 3
// speedup vs baseline: 5.4786x; 1.9583x over previous
#include <cuda_runtime.h>
#include <cuda_bf16.h>
#include <math.h>
#include <stdint.h>

#define BB   4
#define NTOK 4096
#define CC   256
#define DD   32
#define MM   (BB * NTOK)   // 16384

// Scratch (allocation-free per harness rules)
__device__ __nv_bfloat16 g_xb[MM * CC];
__device__ __nv_bfloat16 g_q[MM * DD];
__device__ __nv_bfloat16 g_k[MM * DD];
__device__ __nv_bfloat16 g_v[MM * CC];
__device__ __nv_bfloat16 g_att[MM * CC];
__device__ __nv_bfloat16 g_wqb[CC * DD];
__device__ __nv_bfloat16 g_wkb[CC * DD];
__device__ __nv_bfloat16 g_wvb[CC * CC];
__device__ __nv_bfloat16 g_wob[CC * CC];
__device__ float         g_bqs[DD];

// ---------------------------------------------------------------------------
// PTX helpers
// ---------------------------------------------------------------------------
__device__ __forceinline__ uint32_t smem_u32(const void* p) {
    return (uint32_t)__cvta_generic_to_shared(p);
}
__device__ __forceinline__ void ldsm_x4(uint32_t& r0, uint32_t& r1, uint32_t& r2, uint32_t& r3, uint32_t addr) {
    asm volatile("ldmatrix.sync.aligned.m8n8.x4.shared.b16 {%0,%1,%2,%3}, [%4];\n"
                 : "=r"(r0), "=r"(r1), "=r"(r2), "=r"(r3) : "r"(addr));
}
__device__ __forceinline__ void ldsm_x4_trans(uint32_t& r0, uint32_t& r1, uint32_t& r2, uint32_t& r3, uint32_t addr) {
    asm volatile("ldmatrix.sync.aligned.m8n8.x4.trans.shared.b16 {%0,%1,%2,%3}, [%4];\n"
                 : "=r"(r0), "=r"(r1), "=r"(r2), "=r"(r3) : "r"(addr));
}
__device__ __forceinline__ void mma_bf16(float* c, uint32_t a0, uint32_t a1, uint32_t a2, uint32_t a3,
                                         uint32_t b0, uint32_t b1) {
    asm volatile(
        "mma.sync.aligned.m16n8k16.row.col.f32.bf16.bf16.f32 "
        "{%0,%1,%2,%3}, {%4,%5,%6,%7}, {%8,%9}, {%0,%1,%2,%3};\n"
        : "+f"(c[0]), "+f"(c[1]), "+f"(c[2]), "+f"(c[3])
        : "r"(a0), "r"(a1), "r"(a2), "r"(a3), "r"(b0), "r"(b1));
}
__device__ __forceinline__ void cp_async16(uint32_t smem_dst, const void* gsrc) {
    asm volatile("cp.async.cg.shared.global [%0], [%1], 16;\n" :: "r"(smem_dst), "l"(gsrc));
}
__device__ __forceinline__ void cp_async_commit() { asm volatile("cp.async.commit_group;\n"); }
__device__ __forceinline__ void cp_async_wait0()  { asm volatile("cp.async.wait_group 0;\n"); }

// FFMA-only exp2. Valid for x in ~[-100, 30]. Rel err ~4e-5.
__device__ __forceinline__ float exp2_fast(float x) {
    float fr = x + 12582912.0f;
    int   n  = __float_as_int(fr);
    float f  = x - (fr - 12582912.0f);
    float p  = 0.0096181291f;
    p = fmaf(p, f, 0.0555041087f);
    p = fmaf(p, f, 0.2402265070f);
    p = fmaf(p, f, 0.6931471806f);
    p = fmaf(p, f, 1.0f);
    return __int_as_float(__float_as_int(p) + (n << 23));
}
__device__ __forceinline__ uint32_t pack_bf16(float lo, float hi) {
    __nv_bfloat162 h = __floats2bfloat162_rn(lo, hi);
    return *reinterpret_cast<uint32_t*>(&h);
}

// ---------------------------------------------------------------------------
// fp32 -> bf16 conversion kernels
// ---------------------------------------------------------------------------
__global__ __launch_bounds__(256) void convert_x_kernel(const float4* __restrict__ x, uint2* __restrict__ o) {
    int i = blockIdx.x * 256 + threadIdx.x;
    float4 v = x[i];
    o[i] = make_uint2(pack_bf16(v.x, v.y), pack_bf16(v.z, v.w));
}
__global__ __launch_bounds__(256) void convert_w_kernel(
    const float* __restrict__ wq, const float* __restrict__ bq,
    const float* __restrict__ wk, const float* __restrict__ wv,
    const float* __restrict__ wo, float qscale)
{
    int i = blockIdx.x * 256 + threadIdx.x;
    if (i < CC * CC) {
        g_wvb[i] = __float2bfloat16(wv[i]);
        g_wob[i] = __float2bfloat16(wo[i]);
    }
    if (i < CC * DD) {
        g_wqb[i] = __float2bfloat16(wq[i] * qscale);
        g_wkb[i] = __float2bfloat16(wk[i]);
    }
    if (i < DD) g_bqs[i] = bq[i] * qscale;
}

// ---------------------------------------------------------------------------
// bf16 tensor-core GEMM: Y[M, N] = A[M, 256] @ W[256, N] + bias (+resid).
// CTA tile 128 x CTA_N. K chunks of 32, double-buffered cp.async.
//   CTA_N=128: 8 warps as 4x2, warp tile 32x64.
//   CTA_N=32 : 8 warps as 8x1, warp tile 16x32.
// ---------------------------------------------------------------------------
#define GXS 40   // A tile row stride in bf16 (32 + 8 pad), 80 B

template <int CTA_N, bool OUT_BF16, bool RESID>
__global__ __launch_bounds__(256, 2) void tc_gemm_kernel(
    const __nv_bfloat16* __restrict__ A, const __nv_bfloat16* __restrict__ W,
    const float* __restrict__ bias, const float* __restrict__ resid,
    void* __restrict__ Yv, int N)
{
    constexpr int WS = CTA_N + 8;                 // W tile row stride (bf16)
    constexpr int NW = CTA_N / 8;                 // 16-byte chunks per W row
    constexpr int MW = (CTA_N == 128) ? 2 : 1;    // m16 blocks per warp
    constexpr int NB = (CTA_N == 128) ? 8 : 4;    // n8 blocks per warp

    __shared__ __nv_bfloat16 sA[2][128 * GXS];
    __shared__ __nv_bfloat16 sW[2][32 * WS];

    const int tid  = threadIdx.x;
    const int lane = tid & 31;
    const int warp = tid >> 5;
    const int wm   = (CTA_N == 128) ? (warp >> 1) : warp;   // row group
    const int wn   = (CTA_N == 128) ? (warp & 1) : 0;       // col group
    const int row0 = blockIdx.y * 128;
    const int n0   = blockIdx.x * CTA_N;

    const uint32_t sA_u[2] = { smem_u32(sA[0]), smem_u32(sA[1]) };
    const uint32_t sW_u[2] = { smem_u32(sW[0]), smem_u32(sW[1]) };

    auto load_chunk = [&](int buf, int k0) {
        // A: 128 rows x 32 bf16 = 512 x 16B
        #pragma unroll
        for (int i = 0; i < 2; i++) {
            int idx = tid + i * 256;
            int r = idx >> 2, c = idx & 3;
            cp_async16(sA_u[buf] + r * (GXS * 2) + c * 16,
                       A + (size_t)(row0 + r) * CC + k0 + c * 8);
        }
        // W: 32 rows x CTA_N bf16
        #pragma unroll
        for (int i = 0; i < (32 * NW + 255) / 256; i++) {
            int idx = tid + i * 256;
            if (32 * NW < 256 && idx >= 32 * NW) break;
            int r = idx / NW, c = idx % NW;
            cp_async16(sW_u[buf] + r * (WS * 2) + c * 16,
                       W + (size_t)(k0 + r) * N + n0 + c * 8);
        }
        cp_async_commit();
    };

    load_chunk(0, 0);

    float acc[MW][NB][4];
    #pragma unroll
    for (int m = 0; m < MW; m++)
        #pragma unroll
        for (int nb = 0; nb < NB; nb++)
            #pragma unroll
            for (int q = 0; q < 4; q++) acc[m][nb][q] = 0.0f;

    const int arow = (lane & 15);
    const int acolb = ((lane >> 4) & 1) * 16;
    const int brow = (lane & 7) + ((lane >> 3) & 1) * 8;
    const int bcolb = ((lane >> 4) & 1) * 16;

    for (int ch = 0; ch < 8; ch++) {
        cp_async_wait0();
        __syncthreads();
        if (ch < 7) load_chunk((ch + 1) & 1, (ch + 1) * 32);

        const uint32_t sAb = sA_u[ch & 1];
        const uint32_t sWb = sW_u[ch & 1];

        #pragma unroll
        for (int kk = 0; kk < 2; kk++) {
            uint32_t a[MW][4];
            #pragma unroll
            for (int m = 0; m < MW; m++)
                ldsm_x4(a[m][0], a[m][1], a[m][2], a[m][3],
                        sAb + (wm * (MW * 16) + m * 16 + arow) * (GXS * 2) + kk * 32 + acolb);
            #pragma unroll
            for (int nb2 = 0; nb2 < NB / 2; nb2++) {
                uint32_t b0, b1, b2, b3;
                ldsm_x4_trans(b0, b1, b2, b3,
                              sWb + (kk * 16 + brow) * (WS * 2) + (wn * (NB * 8) + nb2 * 16) * 2 + bcolb);
                #pragma unroll
                for (int m = 0; m < MW; m++) {
                    mma_bf16(acc[m][2 * nb2],     a[m][0], a[m][1], a[m][2], a[m][3], b0, b1);
                    mma_bf16(acc[m][2 * nb2 + 1], a[m][0], a[m][1], a[m][2], a[m][3], b2, b3);
                }
            }
        }
    }

    // epilogue
    #pragma unroll
    for (int m = 0; m < MW; m++) {
        int r0 = row0 + wm * (MW * 16) + m * 16 + (lane >> 2);
        #pragma unroll
        for (int nb = 0; nb < NB; nb++) {
            int col = n0 + wn * (NB * 8) + nb * 8 + (lane & 3) * 2;
            #pragma unroll
            for (int h = 0; h < 2; h++) {      // h=0: row r0, h=1: row r0+8
                int r = r0 + h * 8;
                float c0 = acc[m][nb][2 * h]     + bias[col];
                float c1 = acc[m][nb][2 * h + 1] + bias[col + 1];
                if (RESID) {
                    float2 rr = *(const float2*)&resid[(size_t)r * N + col];
                    c0 += rr.x; c1 += rr.y;
                }
                if (OUT_BF16)
                    *(uint32_t*)&((__nv_bfloat16*)Yv)[(size_t)r * N + col] = pack_bf16(c0, c1);
                else
                    *(float2*)&((float*)Yv)[(size_t)r * N + col] = make_float2(c0, c1);
            }
        }
    }
}

// ---------------------------------------------------------------------------
// Flash attention, bf16 mma, no online max, FFMA exp2, cp.async double buffer.
// ---------------------------------------------------------------------------
#define KSTRIDE 40   // 80 B
#define VSTRIDE 264  // 528 B
#define KBYTES  (64 * KSTRIDE * 2)   // 5120
#define VBYTES  (64 * VSTRIDE * 2)   // 33792

__global__ __launch_bounds__(256, 2) void attn_kernel(
    const __nv_bfloat16* __restrict__ gq, const __nv_bfloat16* __restrict__ gk,
    const __nv_bfloat16* __restrict__ gv, __nv_bfloat16* __restrict__ gatt)
{
    extern __shared__ char smraw[];
    char* sQ = smraw;
    char* sK0 = sQ + KBYTES;
    char* sV0 = sK0 + KBYTES;
    char* sK1 = sV0 + VBYTES;
    char* sV1 = sK1 + KBYTES;

    const int tid  = threadIdx.x;
    const int lane = tid & 31;
    const int warp = tid >> 5;
    const int wm   = warp >> 1;
    const int wn   = warp & 1;

    const int b  = blockIdx.y;
    const int qt = blockIdx.x;

    const __nv_bfloat16* qb = gq + (size_t)b * NTOK * DD + (size_t)qt * 64 * DD;
    const __nv_bfloat16* kb = gk + (size_t)b * NTOK * DD;
    const __nv_bfloat16* vb = gv + (size_t)b * NTOK * CC;

    const uint32_t sQ_u = smem_u32(sQ);
    const uint32_t sK_u[2] = { smem_u32(sK0), smem_u32(sK1) };
    const uint32_t sV_u[2] = { smem_u32(sV0), smem_u32(sV1) };

    // stage Q
    {
        int r = tid >> 2, c8 = tid & 3;
        const uint4* src = (const uint4*)(qb + (size_t)r * DD + c8 * 8);
        *(uint4*)(sQ + r * (KSTRIDE * 2) + c8 * 16) = *src;
    }
    // prologue K/V tile 0
    {
        int r = tid >> 2, c = tid & 3;
        cp_async16(sK_u[0] + r * (KSTRIDE * 2) + c * 16, kb + (size_t)r * DD + c * 8);
        #pragma unroll
        for (int i = 0; i < 8; i++) {
            int idx = tid + i * 256;
            int vr = idx >> 5, vc = idx & 31;
            cp_async16(sV_u[0] + vr * (VSTRIDE * 2) + vc * 16, vb + (size_t)vr * CC + vc * 8);
        }
    }
    cp_async_commit();
    __syncthreads();

    uint32_t qA[2][4];
    {
        int lrow = lane & 15;
        int lcolh = (lane >> 4) << 3;
        uint32_t base = sQ_u + (16 * wm + lrow) * (KSTRIDE * 2) + lcolh * 2;
        ldsm_x4(qA[0][0], qA[0][1], qA[0][2], qA[0][3], base);
        ldsm_x4(qA[1][0], qA[1][1], qA[1][2], qA[1][3], base + 32);
    }

    float acc[16][4];
    #pragma unroll
    for (int j = 0; j < 16; j++)
        #pragma unroll
        for (int q4 = 0; q4 < 4; q4++) acc[j][q4] = 0.0f;
    float lsum0 = 0.0f, lsum1 = 0.0f;

    // x4 (non-trans) K addressing: lanes 0-7 m0, 8-15 m1, 16-23 m2, 24-31 m3
    const int krow4  = ((lane >> 4) & 1) * 8 + (lane & 7);   // key within 16
    const int kcolb4 = ((lane >> 3) & 1) * 16;               // dim-half bytes
    // x4 trans V addressing
    const int vrow4  = (lane & 7) + ((lane >> 3) & 1) * 8;   // k-row within 16
    const int vcolb4 = ((lane >> 4) & 1) * 16;               // col-half bytes

    for (int kt = 0; kt < NTOK / 64; kt++) {
        cp_async_wait0();
        __syncthreads();

        if (kt + 1 < NTOK / 64) {
            int nb = (kt + 1) & 1;
            const __nv_bfloat16* kbt = kb + (size_t)(kt + 1) * 64 * DD;
            const __nv_bfloat16* vbt = vb + (size_t)(kt + 1) * 64 * CC;
            int r = tid >> 2, c = tid & 3;
            cp_async16(sK_u[nb] + r * (KSTRIDE * 2) + c * 16, kbt + (size_t)r * DD + c * 8);
            #pragma unroll
            for (int i = 0; i < 8; i++) {
                int idx = tid + i * 256;
                int vr = idx >> 5, vc = idx & 31;
                cp_async16(sV_u[nb] + vr * (VSTRIDE * 2) + vc * 16, vbt + (size_t)vr * CC + vc * 8);
            }
        }
        cp_async_commit();

        const uint32_t sKb = sK_u[kt & 1];
        const uint32_t sVb = sV_u[kt & 1];

        // S = Q @ K^T
        float sfrag[8][4];
        #pragma unroll
        for (int nt = 0; nt < 8; nt++)
            #pragma unroll
            for (int q4 = 0; q4 < 4; q4++) sfrag[nt][q4] = 0.0f;

        #pragma unroll
        for (int kbk = 0; kbk < 2; kbk++) {
            #pragma unroll
            for (int nt2 = 0; nt2 < 4; nt2++) {
                uint32_t b0, b1, b2, b3;
                ldsm_x4(b0, b1, b2, b3,
                        sKb + (nt2 * 16 + krow4) * (KSTRIDE * 2) + kbk * 32 + kcolb4);
                mma_bf16(sfrag[2 * nt2],     qA[kbk][0], qA[kbk][1], qA[kbk][2], qA[kbk][3], b0, b1);
                mma_bf16(sfrag[2 * nt2 + 1], qA[kbk][0], qA[kbk][1], qA[kbk][2], qA[kbk][3], b2, b3);
            }
        }

        // P = exp2(S)
        uint32_t plo[8], phi[8];
        #pragma unroll
        for (int nt = 0; nt < 8; nt++) {
            float p0 = exp2_fast(sfrag[nt][0]);
            float p1 = exp2_fast(sfrag[nt][1]);
            float p2 = exp2_fast(sfrag[nt][2]);
            float p3 = exp2_fast(sfrag[nt][3]);
            lsum0 += p0 + p1;
            lsum1 += p2 + p3;
            plo[nt] = pack_bf16(p0, p1);
            phi[nt] = pack_bf16(p2, p3);
        }

        // O += P @ V
        #pragma unroll
        for (int kb2 = 0; kb2 < 4; kb2++) {
            uint32_t a0 = plo[2 * kb2], a1 = phi[2 * kb2];
            uint32_t a2 = plo[2 * kb2 + 1], a3 = phi[2 * kb2 + 1];
            #pragma unroll
            for (int j2 = 0; j2 < 8; j2++) {
                uint32_t b0, b1, b2, b3;
                ldsm_x4_trans(b0, b1, b2, b3,
                              sVb + (kb2 * 16 + vrow4) * (VSTRIDE * 2) + wn * 256 + j2 * 32 + vcolb4);
                mma_bf16(acc[2 * j2],     a0, a1, a2, a3, b0, b1);
                mma_bf16(acc[2 * j2 + 1], a0, a1, a2, a3, b2, b3);
            }
        }
    }

    // epilogue
    lsum0 += __shfl_xor_sync(0xFFFFFFFFu, lsum0, 1);
    lsum0 += __shfl_xor_sync(0xFFFFFFFFu, lsum0, 2);
    lsum1 += __shfl_xor_sync(0xFFFFFFFFu, lsum1, 1);
    lsum1 += __shfl_xor_sync(0xFFFFFFFFu, lsum1, 2);
    float inv0 = 1.0f / lsum0;
    float inv1 = 1.0f / lsum1;

    __nv_bfloat16* ob = gatt + (size_t)b * NTOK * CC + (size_t)qt * 64 * CC;
    int row0 = 16 * wm + (lane >> 2);
    int colb = wn * 128 + (lane & 3) * 2;
    #pragma unroll
    for (int j = 0; j < 16; j++) {
        int col = colb + j * 8;
        *(uint32_t*)&ob[(size_t)row0 * CC + col]       = pack_bf16(acc[j][0] * inv0, acc[j][1] * inv0);
        *(uint32_t*)&ob[(size_t)(row0 + 8) * CC + col] = pack_bf16(acc[j][2] * inv1, acc[j][3] * inv1);
    }
}

// ---------------------------------------------------------------------------
extern "C" void kernel_launch(void* const* d_in, const int* in_sizes, int n_in,
                              void* d_out, int out_size)
{
    const float* x  = (const float*)d_in[0];
    const float* wq = (const float*)d_in[1];
    const float* bq = (const float*)d_in[2];
    const float* wk = (const float*)d_in[3];
    const float* bk = (const float*)d_in[4];
    const float* wv = (const float*)d_in[5];
    const float* bv = (const float*)d_in[6];
    const float* wo = (const float*)d_in[7];
    const float* bo = (const float*)d_in[8];
    float* out = (float*)d_out;

    __nv_bfloat16 *xb, *q, *k, *v, *att, *wqb, *wkb, *wvb, *wob;
    float* bqs;
    cudaGetSymbolAddress((void**)&xb,  g_xb);
    cudaGetSymbolAddress((void**)&q,   g_q);
    cudaGetSymbolAddress((void**)&k,   g_k);
    cudaGetSymbolAddress((void**)&v,   g_v);
    cudaGetSymbolAddress((void**)&att, g_att);
    cudaGetSymbolAddress((void**)&wqb, g_wqb);
    cudaGetSymbolAddress((void**)&wkb, g_wkb);
    cudaGetSymbolAddress((void**)&wvb, g_wvb);
    cudaGetSymbolAddress((void**)&wob, g_wob);
    cudaGetSymbolAddress((void**)&bqs, g_bqs);

    dim3 blk(256);
    const float qscale = 1.4426950408889634f / 5.656854249492380f;  // log2(e)/sqrt(32)

    convert_x_kernel<<<MM * CC / 4 / 256, blk>>>((const float4*)x, (uint2*)xb);
    convert_w_kernel<<<CC * CC / 256, blk>>>(wq, bq, wk, wv, wo, qscale);

    // projections (bf16 tensor cores)
    tc_gemm_kernel<32,  true, false><<<dim3(1, MM / 128), blk>>>(xb, wqb, bqs, nullptr, q, DD);
    tc_gemm_kernel<32,  true, false><<<dim3(1, MM / 128), blk>>>(xb, wkb, bk,  nullptr, k, DD);
    tc_gemm_kernel<128, true, false><<<dim3(2, MM / 128), blk>>>(xb, wvb, bv,  nullptr, v, CC);

    // attention
    size_t smem = KBYTES + 2 * (KBYTES + VBYTES);   // 82944 B
    cudaFuncSetAttribute(attn_kernel, cudaFuncAttributeMaxDynamicSharedMemorySize, (int)smem);
    attn_kernel<<<dim3(NTOK / 64, BB), blk, smem>>>(q, k, v, att);

    // output projection + bias + residual (fp32 out)
    tc_gemm_kernel<128, false, true><<<dim3(2, MM / 128), blk>>>(att, wob, bo, x, out, CC);
}

// round 4
// speedup vs baseline: 6.5063x; 1.1876x over previous
#include <cuda_runtime.h>
#include <cuda_bf16.h>
#include <math.h>
#include <stdint.h>

#define BB   4
#define NTOK 4096
#define CC   256
#define DD   32
#define MM   (BB * NTOK)   // 16384

// Scratch (allocation-free per harness rules)
__device__ __nv_bfloat16 g_xb[MM * CC];
__device__ __nv_bfloat16 g_q[MM * DD];
__device__ __nv_bfloat16 g_k[MM * DD];
__device__ __nv_bfloat16 g_v[MM * CC];
__device__ __nv_bfloat16 g_att[MM * CC];
__device__ __nv_bfloat16 g_wqkb[CC * 64];   // [256, 64]: cols 0-31 wq*qscale, 32-63 wk
__device__ __nv_bfloat16 g_wvb[CC * CC];
__device__ __nv_bfloat16 g_wob[CC * CC];
__device__ float         g_bqk[64];

// ---------------------------------------------------------------------------
// PTX helpers
// ---------------------------------------------------------------------------
__device__ __forceinline__ uint32_t smem_u32(const void* p) {
    return (uint32_t)__cvta_generic_to_shared(p);
}
__device__ __forceinline__ void ldsm_x4(uint32_t& r0, uint32_t& r1, uint32_t& r2, uint32_t& r3, uint32_t addr) {
    asm volatile("ldmatrix.sync.aligned.m8n8.x4.shared.b16 {%0,%1,%2,%3}, [%4];\n"
                 : "=r"(r0), "=r"(r1), "=r"(r2), "=r"(r3) : "r"(addr));
}
__device__ __forceinline__ void ldsm_x4_trans(uint32_t& r0, uint32_t& r1, uint32_t& r2, uint32_t& r3, uint32_t addr) {
    asm volatile("ldmatrix.sync.aligned.m8n8.x4.trans.shared.b16 {%0,%1,%2,%3}, [%4];\n"
                 : "=r"(r0), "=r"(r1), "=r"(r2), "=r"(r3) : "r"(addr));
}
__device__ __forceinline__ void mma_bf16(float* c, uint32_t a0, uint32_t a1, uint32_t a2, uint32_t a3,
                                         uint32_t b0, uint32_t b1) {
    asm volatile(
        "mma.sync.aligned.m16n8k16.row.col.f32.bf16.bf16.f32 "
        "{%0,%1,%2,%3}, {%4,%5,%6,%7}, {%8,%9}, {%0,%1,%2,%3};\n"
        : "+f"(c[0]), "+f"(c[1]), "+f"(c[2]), "+f"(c[3])
        : "r"(a0), "r"(a1), "r"(a2), "r"(a3), "r"(b0), "r"(b1));
}
__device__ __forceinline__ void cp_async16(uint32_t smem_dst, const void* gsrc) {
    asm volatile("cp.async.cg.shared.global [%0], [%1], 16;\n" :: "r"(smem_dst), "l"(gsrc));
}
__device__ __forceinline__ void cp_async_commit() { asm volatile("cp.async.commit_group;\n"); }
__device__ __forceinline__ void cp_async_wait0()  { asm volatile("cp.async.wait_group 0;\n"); }

__device__ __forceinline__ uint32_t pack_bf16(float lo, float hi) {
    __nv_bfloat162 h = __floats2bfloat162_rn(lo, hi);
    return *reinterpret_cast<uint32_t*>(&h);
}

// packed f32x2 ops (sm_103a; FFMA2 only reachable via PTX)
__device__ __forceinline__ uint64_t pk2f(float v) {
    uint32_t b = __float_as_uint(v);
    return ((uint64_t)b << 32) | b;
}
__device__ __forceinline__ uint64_t f32x2_add(uint64_t a, uint64_t b) {
    uint64_t d; asm("add.rn.f32x2 %0, %1, %2;" : "=l"(d) : "l"(a), "l"(b)); return d;
}
__device__ __forceinline__ uint64_t f32x2_fma(uint64_t a, uint64_t b, uint64_t c) {
    uint64_t d; asm("fma.rn.f32x2 %0, %1, %2, %3;" : "=l"(d) : "l"(a), "l"(b), "l"(c)); return d;
}

// Two exp2's in packed f32x2, result as bf16x2 (lo = exp2(x0)). FFMA-only.
__device__ __forceinline__ uint32_t exp2_pair_bf16(float x0, float x1) {
    uint64_t X2; asm("mov.b64 %0, {%1, %2};" : "=l"(X2) : "f"(x0), "f"(x1));
    uint64_t fr2 = f32x2_add(X2, pk2f(12582912.0f));
    uint64_t t2  = f32x2_add(fr2, pk2f(-12582912.0f));
    uint64_t f2  = f32x2_fma(t2, pk2f(-1.0f), X2);            // f = x - round(x)
    uint64_t p2  = f32x2_fma(pk2f(0.0096181291f), f2, pk2f(0.0555041087f));
    p2 = f32x2_fma(p2, f2, pk2f(0.2402265070f));
    p2 = f32x2_fma(p2, f2, pk2f(0.6931471806f));
    p2 = f32x2_fma(p2, f2, pk2f(1.0f));
    uint32_t fr0, fr1, pp0, pp1;
    asm("mov.b64 {%0, %1}, %2;" : "=r"(fr0), "=r"(fr1) : "l"(fr2));
    asm("mov.b64 {%0, %1}, %2;" : "=r"(pp0), "=r"(pp1) : "l"(p2));
    float e0 = __int_as_float(pp0 + (fr0 << 23));             // exponent inject
    float e1 = __int_as_float(pp1 + (fr1 << 23));
    uint32_t r; asm("cvt.rn.bf16x2.f32 %0, %1, %2;" : "=r"(r) : "f"(e1), "f"(e0));
    return r;
}

// ---------------------------------------------------------------------------
// fp32 -> bf16 conversion kernels
// ---------------------------------------------------------------------------
__global__ __launch_bounds__(256) void convert_x_kernel(const float4* __restrict__ x, uint2* __restrict__ o) {
    int i = blockIdx.x * 256 + threadIdx.x;
    float4 v = x[i];
    o[i] = make_uint2(pack_bf16(v.x, v.y), pack_bf16(v.z, v.w));
}
__global__ __launch_bounds__(256) void convert_w_kernel(
    const float* __restrict__ wq, const float* __restrict__ bq,
    const float* __restrict__ wk, const float* __restrict__ bk,
    const float* __restrict__ wv, const float* __restrict__ wo, float qscale)
{
    int i = blockIdx.x * 256 + threadIdx.x;
    if (i < CC * CC) {
        g_wvb[i] = __float2bfloat16(wv[i]);
        g_wob[i] = __float2bfloat16(wo[i]);
    }
    if (i < CC * 64) {
        int r = i >> 6, c = i & 63;
        g_wqkb[i] = (c < 32) ? __float2bfloat16(wq[r * DD + c] * qscale)
                             : __float2bfloat16(wk[r * DD + c - 32]);
    }
    if (i < 64) g_bqk[i] = (i < 32) ? bq[i] * qscale : bk[i - 32];
}

// ---------------------------------------------------------------------------
// bf16 tensor-core GEMM. MODE: 0 = bf16 out, 1 = fp32 out + resid, 2 = split
// Q/K bf16 out (cols 0-31 -> Yv, 32-63 -> Y2).
// ---------------------------------------------------------------------------
#define GXS 40   // A tile row stride (bf16)

template <int CTA_N, int MODE>
__global__ __launch_bounds__(256, 2) void tc_gemm_kernel(
    const __nv_bfloat16* __restrict__ A, const __nv_bfloat16* __restrict__ W,
    const float* __restrict__ bias, const float* __restrict__ resid,
    void* __restrict__ Yv, void* __restrict__ Y2, int N)
{
    constexpr int WS = CTA_N + 8;
    constexpr int NW = CTA_N / 8;
    constexpr int MW = 2;
    constexpr int NB = (CTA_N == 128) ? 8 : 4;
    constexpr int WM_GROUPS = 4;

    __shared__ __nv_bfloat16 sA[2][128 * GXS];
    __shared__ __nv_bfloat16 sW[2][32 * WS];

    const int tid  = threadIdx.x;
    const int lane = tid & 31;
    const int warp = tid >> 5;
    const int wm   = warp >> 1;
    const int wn   = warp & 1;
    const int row0 = blockIdx.y * 128;
    const int n0   = blockIdx.x * CTA_N;

    const uint32_t sA_u[2] = { smem_u32(sA[0]), smem_u32(sA[1]) };
    const uint32_t sW_u[2] = { smem_u32(sW[0]), smem_u32(sW[1]) };

    auto load_chunk = [&](int buf, int k0) {
        #pragma unroll
        for (int i = 0; i < 2; i++) {
            int idx = tid + i * 256;
            int r = idx >> 2, c = idx & 3;
            cp_async16(sA_u[buf] + r * (GXS * 2) + c * 16,
                       A + (size_t)(row0 + r) * CC + k0 + c * 8);
        }
        #pragma unroll
        for (int i = 0; i < (32 * NW + 255) / 256; i++) {
            int idx = tid + i * 256;
            int r = idx / NW, c = idx % NW;
            cp_async16(sW_u[buf] + r * (WS * 2) + c * 16,
                       W + (size_t)(k0 + r) * N + n0 + c * 8);
        }
        cp_async_commit();
    };

    load_chunk(0, 0);

    float acc[MW][NB][4];
    #pragma unroll
    for (int m = 0; m < MW; m++)
        #pragma unroll
        for (int nb = 0; nb < NB; nb++)
            #pragma unroll
            for (int q = 0; q < 4; q++) acc[m][nb][q] = 0.0f;

    const int arow = (lane & 15);
    const int acolb = ((lane >> 4) & 1) * 16;
    const int brow = (lane & 7) + ((lane >> 3) & 1) * 8;
    const int bcolb = ((lane >> 4) & 1) * 16;

    for (int ch = 0; ch < 8; ch++) {
        cp_async_wait0();
        __syncthreads();
        if (ch < 7) load_chunk((ch + 1) & 1, (ch + 1) * 32);

        const uint32_t sAb = sA_u[ch & 1];
        const uint32_t sWb = sW_u[ch & 1];

        #pragma unroll
        for (int kk = 0; kk < 2; kk++) {
            uint32_t a[MW][4];
            #pragma unroll
            for (int m = 0; m < MW; m++)
                ldsm_x4(a[m][0], a[m][1], a[m][2], a[m][3],
                        sAb + (wm * (MW * 16) + m * 16 + arow) * (GXS * 2) + kk * 32 + acolb);
            #pragma unroll
            for (int nb2 = 0; nb2 < NB / 2; nb2++) {
                uint32_t b0, b1, b2, b3;
                ldsm_x4_trans(b0, b1, b2, b3,
                              sWb + (kk * 16 + brow) * (WS * 2) + (wn * (NB * 8) + nb2 * 16) * 2 + bcolb);
                #pragma unroll
                for (int m = 0; m < MW; m++) {
                    mma_bf16(acc[m][2 * nb2],     a[m][0], a[m][1], a[m][2], a[m][3], b0, b1);
                    mma_bf16(acc[m][2 * nb2 + 1], a[m][0], a[m][1], a[m][2], a[m][3], b2, b3);
                }
            }
        }
    }

    #pragma unroll
    for (int m = 0; m < MW; m++) {
        int r0 = row0 + wm * (MW * 16) + m * 16 + (lane >> 2);
        #pragma unroll
        for (int nb = 0; nb < NB; nb++) {
            int col = n0 + wn * (NB * 8) + nb * 8 + (lane & 3) * 2;
            #pragma unroll
            for (int h = 0; h < 2; h++) {
                int r = r0 + h * 8;
                float c0 = acc[m][nb][2 * h]     + bias[col];
                float c1 = acc[m][nb][2 * h + 1] + bias[col + 1];
                if (MODE == 1) {
                    float2 rr = *(const float2*)&resid[(size_t)r * N + col];
                    *(float2*)&((float*)Yv)[(size_t)r * N + col] = make_float2(c0 + rr.x, c1 + rr.y);
                } else if (MODE == 0) {
                    *(uint32_t*)&((__nv_bfloat16*)Yv)[(size_t)r * N + col] = pack_bf16(c0, c1);
                } else {  // split q/k
                    if (col < 32)
                        *(uint32_t*)&((__nv_bfloat16*)Yv)[(size_t)r * DD + col] = pack_bf16(c0, c1);
                    else
                        *(uint32_t*)&((__nv_bfloat16*)Y2)[(size_t)r * DD + col - 32] = pack_bf16(c0, c1);
                }
            }
        }
    }
}

// ---------------------------------------------------------------------------
// Flash attention: bf16 mma, no online max, packed-f32x2 exp2, S-split across
// warp pairs with smem P exchange, row sums via ones-MMA, cp.async 2-buffer.
// ---------------------------------------------------------------------------
#define KSTRIDE 40    // 80 B
#define VSTRIDE 264   // 528 B
#define KBYTES  (64 * KSTRIDE * 2)   // 5120
#define VBYTES  (64 * VSTRIDE * 2)   // 33792
#define PSTRIDE 72    // P row stride (bf16): 64 + 8 pad -> 144 B
#define PBYTES  (16 * PSTRIDE * 2)   // 2304 per wm group
#define ONE2BF  0x3F803F80u

__global__ __launch_bounds__(256, 2) void attn_kernel(
    const __nv_bfloat16* __restrict__ gq, const __nv_bfloat16* __restrict__ gk,
    const __nv_bfloat16* __restrict__ gv, __nv_bfloat16* __restrict__ gatt)
{
    extern __shared__ char smraw[];
    char* sQ  = smraw;
    char* sK0 = sQ + KBYTES;
    char* sV0 = sK0 + KBYTES;
    char* sK1 = sV0 + VBYTES;
    char* sV1 = sK1 + KBYTES;
    char* sP  = sV1 + VBYTES;          // 4 * PBYTES

    const int tid  = threadIdx.x;
    const int lane = tid & 31;
    const int warp = tid >> 5;
    const int wm   = warp >> 1;        // 0..3 -> rows 16*wm
    const int wn   = warp & 1;         // 0..1 -> key half / V-col half

    const int b  = blockIdx.y;
    const int qt = blockIdx.x;

    const __nv_bfloat16* qb = gq + (size_t)b * NTOK * DD + (size_t)qt * 64 * DD;
    const __nv_bfloat16* kb = gk + (size_t)b * NTOK * DD;
    const __nv_bfloat16* vb = gv + (size_t)b * NTOK * CC;

    const uint32_t sQ_u = smem_u32(sQ);
    const uint32_t sK_u[2] = { smem_u32(sK0), smem_u32(sK1) };
    const uint32_t sV_u[2] = { smem_u32(sV0), smem_u32(sV1) };
    const uint32_t sP_u = smem_u32(sP) + wm * PBYTES;

    // stage Q
    {
        int r = tid >> 2, c8 = tid & 3;
        *(uint4*)(sQ + r * (KSTRIDE * 2) + c8 * 16) = *(const uint4*)(qb + (size_t)r * DD + c8 * 8);
    }
    // prologue K/V tile 0
    {
        int r = tid >> 2, c = tid & 3;
        cp_async16(sK_u[0] + r * (KSTRIDE * 2) + c * 16, kb + (size_t)r * DD + c * 8);
        #pragma unroll
        for (int i = 0; i < 8; i++) {
            int idx = tid + i * 256;
            int vr = idx >> 5, vc = idx & 31;
            cp_async16(sV_u[0] + vr * (VSTRIDE * 2) + vc * 16, vb + (size_t)vr * CC + vc * 8);
        }
    }
    cp_async_commit();
    __syncthreads();

    uint32_t qA[2][4];
    {
        uint32_t base = sQ_u + (16 * wm + (lane & 15)) * (KSTRIDE * 2) + ((lane >> 4) & 1) * 16;
        ldsm_x4(qA[0][0], qA[0][1], qA[0][2], qA[0][3], base);
        ldsm_x4(qA[1][0], qA[1][1], qA[1][2], qA[1][3], base + 32);
    }

    float acc[16][4];
    #pragma unroll
    for (int j = 0; j < 16; j++)
        #pragma unroll
        for (int q4 = 0; q4 < 4; q4++) acc[j][q4] = 0.0f;
    float acc_ones[4] = {0.0f, 0.0f, 0.0f, 0.0f};

    const int krow4  = ((lane >> 4) & 1) * 8 + (lane & 7);
    const int kcolb4 = ((lane >> 3) & 1) * 16;
    const int vrow4  = (lane & 7) + ((lane >> 3) & 1) * 8;
    const int vcolb4 = ((lane >> 4) & 1) * 16;

    for (int kt = 0; kt < NTOK / 64; kt++) {
        cp_async_wait0();
        __syncthreads();

        if (kt + 1 < NTOK / 64) {
            int nb = (kt + 1) & 1;
            const __nv_bfloat16* kbt = kb + (size_t)(kt + 1) * 64 * DD;
            const __nv_bfloat16* vbt = vb + (size_t)(kt + 1) * 64 * CC;
            int r = tid >> 2, c = tid & 3;
            cp_async16(sK_u[nb] + r * (KSTRIDE * 2) + c * 16, kbt + (size_t)r * DD + c * 8);
            #pragma unroll
            for (int i = 0; i < 8; i++) {
                int idx = tid + i * 256;
                int vr = idx >> 5, vc = idx & 31;
                cp_async16(sV_u[nb] + vr * (VSTRIDE * 2) + vc * 16, vbt + (size_t)vr * CC + vc * 8);
            }
        }
        cp_async_commit();

        const uint32_t sKb = sK_u[kt & 1];
        const uint32_t sVb = sV_u[kt & 1];

        // ---- S = Q @ K^T for this warp's 32-key half ----
        float sfrag[4][4];
        #pragma unroll
        for (int nt = 0; nt < 4; nt++)
            #pragma unroll
            for (int q4 = 0; q4 < 4; q4++) sfrag[nt][q4] = 0.0f;

        #pragma unroll
        for (int kbk = 0; kbk < 2; kbk++) {
            #pragma unroll
            for (int nt2 = 0; nt2 < 2; nt2++) {
                uint32_t b0, b1, b2, b3;
                ldsm_x4(b0, b1, b2, b3,
                        sKb + (wn * 32 + nt2 * 16 + krow4) * (KSTRIDE * 2) + kbk * 32 + kcolb4);
                mma_bf16(sfrag[2 * nt2],     qA[kbk][0], qA[kbk][1], qA[kbk][2], qA[kbk][3], b0, b1);
                mma_bf16(sfrag[2 * nt2 + 1], qA[kbk][0], qA[kbk][1], qA[kbk][2], qA[kbk][3], b2, b3);
            }
        }

        // ---- P = exp2(S) (packed pairs), store bf16 P to smem ----
        {
            uint32_t prow = lane >> 2;
            uint32_t pbase = sP_u + prow * (PSTRIDE * 2) + (wn * 32 + (lane & 3) * 2) * 2;
            #pragma unroll
            for (int nt = 0; nt < 4; nt++) {
                uint32_t pb_lo = exp2_pair_bf16(sfrag[nt][0], sfrag[nt][1]);
                uint32_t pb_hi = exp2_pair_bf16(sfrag[nt][2], sfrag[nt][3]);
                uint32_t a0 = pbase + nt * 16;
                *(uint32_t*)(smraw + (a0 - smem_u32(smraw))) = pb_lo;          // row prow
                *(uint32_t*)(smraw + (a0 + 8 * (PSTRIDE * 2) - smem_u32(smraw))) = pb_hi; // row prow+8
            }
        }
        asm volatile("bar.sync %0, %1;" :: "r"(wm + 1), "r"(64) : "memory");

        // ---- O += P @ V (full 64 keys; P from smem) + ones-MMA row sums ----
        #pragma unroll
        for (int kb2 = 0; kb2 < 4; kb2++) {
            uint32_t a0, a1, a2, a3;
            ldsm_x4(a0, a1, a2, a3,
                    sP_u + (lane & 15) * (PSTRIDE * 2) + kb2 * 32 + ((lane >> 4) & 1) * 16);
            mma_bf16(acc_ones, a0, a1, a2, a3, ONE2BF, ONE2BF);
            #pragma unroll
            for (int j2 = 0; j2 < 8; j2++) {
                uint32_t b0, b1, b2, b3;
                ldsm_x4_trans(b0, b1, b2, b3,
                              sVb + (kb2 * 16 + vrow4) * (VSTRIDE * 2) + wn * 256 + j2 * 32 + vcolb4);
                mma_bf16(acc[2 * j2],     a0, a1, a2, a3, b0, b1);
                mma_bf16(acc[2 * j2 + 1], a0, a1, a2, a3, b2, b3);
            }
        }
    }

    // epilogue: acc_ones[0]/[2] hold full row sums for rows r0 / r0+8
    float inv0 = 1.0f / acc_ones[0];
    float inv1 = 1.0f / acc_ones[2];

    __nv_bfloat16* ob = gatt + (size_t)b * NTOK * CC + (size_t)qt * 64 * CC;
    int row0 = 16 * wm + (lane >> 2);
    int colb = wn * 128 + (lane & 3) * 2;
    #pragma unroll
    for (int j = 0; j < 16; j++) {
        int col = colb + j * 8;
        *(uint32_t*)&ob[(size_t)row0 * CC + col]       = pack_bf16(acc[j][0] * inv0, acc[j][1] * inv0);
        *(uint32_t*)&ob[(size_t)(row0 + 8) * CC + col] = pack_bf16(acc[j][2] * inv1, acc[j][3] * inv1);
    }
}

// ---------------------------------------------------------------------------
extern "C" void kernel_launch(void* const* d_in, const int* in_sizes, int n_in,
                              void* d_out, int out_size)
{
    const float* x  = (const float*)d_in[0];
    const float* wq = (const float*)d_in[1];
    const float* bq = (const float*)d_in[2];
    const float* wk = (const float*)d_in[3];
    const float* bk = (const float*)d_in[4];
    const float* wv = (const float*)d_in[5];
    const float* bv = (const float*)d_in[6];
    const float* wo = (const float*)d_in[7];
    const float* bo = (const float*)d_in[8];
    float* out = (float*)d_out;

    __nv_bfloat16 *xb, *q, *k, *v, *att, *wqkb, *wvb, *wob;
    float* bqk;
    cudaGetSymbolAddress((void**)&xb,   g_xb);
    cudaGetSymbolAddress((void**)&q,    g_q);
    cudaGetSymbolAddress((void**)&k,    g_k);
    cudaGetSymbolAddress((void**)&v,    g_v);
    cudaGetSymbolAddress((void**)&att,  g_att);
    cudaGetSymbolAddress((void**)&wqkb, g_wqkb);
    cudaGetSymbolAddress((void**)&wvb,  g_wvb);
    cudaGetSymbolAddress((void**)&wob,  g_wob);
    cudaGetSymbolAddress((void**)&bqk,  g_bqk);

    dim3 blk(256);
    const float qscale = 1.4426950408889634f / 5.656854249492380f;  // log2(e)/sqrt(32)

    convert_x_kernel<<<MM * CC / 4 / 256, blk>>>((const float4*)x, (uint2*)xb);
    convert_w_kernel<<<CC * CC / 256, blk>>>(wq, bq, wk, bk, wv, wo, qscale);

    // fused Q|K projection, then V projection
    tc_gemm_kernel<64, 2><<<dim3(1, MM / 128), blk>>>(xb, wqkb, bqk, nullptr, q, k, 64);
    tc_gemm_kernel<128, 0><<<dim3(2, MM / 128), blk>>>(xb, wvb, bv, nullptr, v, nullptr, CC);

    // attention
    size_t smem = KBYTES + 2 * (KBYTES + VBYTES) + 4 * PBYTES;   // 92160 B
    cudaFuncSetAttribute(attn_kernel, cudaFuncAttributeMaxDynamicSharedMemorySize, (int)smem);
    attn_kernel<<<dim3(NTOK / 64, BB), blk, smem>>>(q, k, v, att);

    // output projection + bias + residual
    tc_gemm_kernel<128, 1><<<dim3(2, MM / 128), blk>>>(att, wob, bo, x, out, nullptr, CC);
}

// round 7
// speedup vs baseline: 7.2888x; 1.1203x over previous
#include <cuda_runtime.h>
#include <cuda_bf16.h>
#include <math.h>
#include <stdint.h>

#define BB   4
#define NTOK 4096
#define CC   256
#define DD   32
#define MM   (BB * NTOK)   // 16384

// Scratch (allocation-free per harness rules)
__device__ __nv_bfloat16 g_xb[MM * CC];
__device__ __nv_bfloat16 g_q[MM * DD];
__device__ __nv_bfloat16 g_k[MM * DD];
__device__ __nv_bfloat16 g_v[MM * CC];
__device__ __nv_bfloat16 g_att[MM * CC];
__device__ __nv_bfloat16 g_wqkb[CC * 64];   // [256, 64]: cols 0-31 wq*qscale, 32-63 wk
__device__ __nv_bfloat16 g_wvb[CC * CC];
__device__ __nv_bfloat16 g_wob[CC * CC];
__device__ float         g_bqk[64];

// ---------------------------------------------------------------------------
// PTX helpers
// ---------------------------------------------------------------------------
__device__ __forceinline__ uint32_t smem_u32(const void* p) {
    return (uint32_t)__cvta_generic_to_shared(p);
}
__device__ __forceinline__ void ldsm_x4(uint32_t& r0, uint32_t& r1, uint32_t& r2, uint32_t& r3, uint32_t addr) {
    asm volatile("ldmatrix.sync.aligned.m8n8.x4.shared.b16 {%0,%1,%2,%3}, [%4];\n"
                 : "=r"(r0), "=r"(r1), "=r"(r2), "=r"(r3) : "r"(addr));
}
__device__ __forceinline__ void ldsm_x4_trans(uint32_t& r0, uint32_t& r1, uint32_t& r2, uint32_t& r3, uint32_t addr) {
    asm volatile("ldmatrix.sync.aligned.m8n8.x4.trans.shared.b16 {%0,%1,%2,%3}, [%4];\n"
                 : "=r"(r0), "=r"(r1), "=r"(r2), "=r"(r3) : "r"(addr));
}
__device__ __forceinline__ void mma_bf16(float* c, uint32_t a0, uint32_t a1, uint32_t a2, uint32_t a3,
                                         uint32_t b0, uint32_t b1) {
    asm volatile(
        "mma.sync.aligned.m16n8k16.row.col.f32.bf16.bf16.f32 "
        "{%0,%1,%2,%3}, {%4,%5,%6,%7}, {%8,%9}, {%0,%1,%2,%3};\n"
        : "+f"(c[0]), "+f"(c[1]), "+f"(c[2]), "+f"(c[3])
        : "r"(a0), "r"(a1), "r"(a2), "r"(a3), "r"(b0), "r"(b1));
}
__device__ __forceinline__ void cp_async16(uint32_t smem_dst, const void* gsrc) {
    asm volatile("cp.async.cg.shared.global [%0], [%1], 16;\n" :: "r"(smem_dst), "l"(gsrc));
}
__device__ __forceinline__ void cp_async_commit() { asm volatile("cp.async.commit_group;\n"); }
__device__ __forceinline__ void cp_async_wait0()  { asm volatile("cp.async.wait_group 0;\n"); }

__device__ __forceinline__ uint32_t pack_bf16(float lo, float hi) {
    uint32_t r;
    asm("cvt.rn.bf16x2.f32 %0, %1, %2;" : "=r"(r) : "f"(hi), "f"(lo));
    return r;
}
__device__ __forceinline__ float ex2_fast(float x) {
    float y;
    asm("ex2.approx.ftz.f32 %0, %1;" : "=f"(y) : "f"(x));
    return y;
}

// ---------------------------------------------------------------------------
// fp32 -> bf16 conversion kernels
// ---------------------------------------------------------------------------
__global__ __launch_bounds__(256) void convert_x_kernel(const float4* __restrict__ x, uint2* __restrict__ o) {
    int i = blockIdx.x * 256 + threadIdx.x;
    float4 v = x[i];
    o[i] = make_uint2(pack_bf16(v.x, v.y), pack_bf16(v.z, v.w));
}
__global__ __launch_bounds__(256) void convert_w_kernel(
    const float* __restrict__ wq, const float* __restrict__ bq,
    const float* __restrict__ wk, const float* __restrict__ bk,
    const float* __restrict__ wv, const float* __restrict__ wo, float qscale)
{
    int i = blockIdx.x * 256 + threadIdx.x;
    if (i < CC * CC) {
        g_wvb[i] = __float2bfloat16(wv[i]);
        g_wob[i] = __float2bfloat16(wo[i]);
    }
    if (i < CC * 64) {
        int r = i >> 6, c = i & 63;
        g_wqkb[i] = (c < 32) ? __float2bfloat16(wq[r * DD + c] * qscale)
                             : __float2bfloat16(wk[r * DD + c - 32]);
    }
    if (i < 64) g_bqk[i] = (i < 32) ? bq[i] * qscale : bk[i - 32];
}

// ---------------------------------------------------------------------------
// bf16 tensor-core GEMM. MODE: 0 = bf16 out, 1 = fp32 out + resid, 2 = split
// Q/K bf16 out (cols 0-31 -> Yv, 32-63 -> Y2).
// ---------------------------------------------------------------------------
#define GXS 40   // A tile row stride (bf16)

template <int CTA_N, int MODE>
__global__ __launch_bounds__(256, 2) void tc_gemm_kernel(
    const __nv_bfloat16* __restrict__ A, const __nv_bfloat16* __restrict__ W,
    const float* __restrict__ bias, const float* __restrict__ resid,
    void* __restrict__ Yv, void* __restrict__ Y2, int N)
{
    constexpr int WS = CTA_N + 8;
    constexpr int NW = CTA_N / 8;
    constexpr int MW = 2;
    constexpr int NB = (CTA_N == 128) ? 8 : 4;

    __shared__ __nv_bfloat16 sA[2][128 * GXS];
    __shared__ __nv_bfloat16 sW[2][32 * WS];

    const int tid  = threadIdx.x;
    const int lane = tid & 31;
    const int warp = tid >> 5;
    const int wm   = warp >> 1;
    const int wn   = warp & 1;
    const int row0 = blockIdx.y * 128;
    const int n0   = blockIdx.x * CTA_N;

    const uint32_t sA_u[2] = { smem_u32(sA[0]), smem_u32(sA[1]) };
    const uint32_t sW_u[2] = { smem_u32(sW[0]), smem_u32(sW[1]) };

    auto load_chunk = [&](int buf, int k0) {
        #pragma unroll
        for (int i = 0; i < 2; i++) {
            int idx = tid + i * 256;
            int r = idx >> 2, c = idx & 3;
            cp_async16(sA_u[buf] + r * (GXS * 2) + c * 16,
                       A + (size_t)(row0 + r) * CC + k0 + c * 8);
        }
        #pragma unroll
        for (int i = 0; i < (32 * NW + 255) / 256; i++) {
            int idx = tid + i * 256;
            int r = idx / NW, c = idx % NW;
            cp_async16(sW_u[buf] + r * (WS * 2) + c * 16,
                       W + (size_t)(k0 + r) * N + n0 + c * 8);
        }
        cp_async_commit();
    };

    load_chunk(0, 0);

    float acc[MW][NB][4];
    #pragma unroll
    for (int m = 0; m < MW; m++)
        #pragma unroll
        for (int nb = 0; nb < NB; nb++)
            #pragma unroll
            for (int q = 0; q < 4; q++) acc[m][nb][q] = 0.0f;

    const int arow = (lane & 15);
    const int acolb = ((lane >> 4) & 1) * 16;
    const int brow = (lane & 7) + ((lane >> 3) & 1) * 8;
    const int bcolb = ((lane >> 4) & 1) * 16;

    for (int ch = 0; ch < 8; ch++) {
        cp_async_wait0();
        __syncthreads();
        if (ch < 7) load_chunk((ch + 1) & 1, (ch + 1) * 32);

        const uint32_t sAb = sA_u[ch & 1];
        const uint32_t sWb = sW_u[ch & 1];

        #pragma unroll
        for (int kk = 0; kk < 2; kk++) {
            uint32_t a[MW][4];
            #pragma unroll
            for (int m = 0; m < MW; m++)
                ldsm_x4(a[m][0], a[m][1], a[m][2], a[m][3],
                        sAb + (wm * (MW * 16) + m * 16 + arow) * (GXS * 2) + kk * 32 + acolb);
            #pragma unroll
            for (int nb2 = 0; nb2 < NB / 2; nb2++) {
                uint32_t b0, b1, b2, b3;
                ldsm_x4_trans(b0, b1, b2, b3,
                              sWb + (kk * 16 + brow) * (WS * 2) + (wn * (NB * 8) + nb2 * 16) * 2 + bcolb);
                #pragma unroll
                for (int m = 0; m < MW; m++) {
                    mma_bf16(acc[m][2 * nb2],     a[m][0], a[m][1], a[m][2], a[m][3], b0, b1);
                    mma_bf16(acc[m][2 * nb2 + 1], a[m][0], a[m][1], a[m][2], a[m][3], b2, b3);
                }
            }
        }
    }

    #pragma unroll
    for (int m = 0; m < MW; m++) {
        int r0 = row0 + wm * (MW * 16) + m * 16 + (lane >> 2);
        #pragma unroll
        for (int nb = 0; nb < NB; nb++) {
            int col = n0 + wn * (NB * 8) + nb * 8 + (lane & 3) * 2;
            #pragma unroll
            for (int h = 0; h < 2; h++) {
                int r = r0 + h * 8;
                float c0 = acc[m][nb][2 * h]     + bias[col];
                float c1 = acc[m][nb][2 * h + 1] + bias[col + 1];
                if (MODE == 1) {
                    float2 rr = *(const float2*)&resid[(size_t)r * N + col];
                    *(float2*)&((float*)Yv)[(size_t)r * N + col] = make_float2(c0 + rr.x, c1 + rr.y);
                } else if (MODE == 0) {
                    *(uint32_t*)&((__nv_bfloat16*)Yv)[(size_t)r * N + col] = pack_bf16(c0, c1);
                } else {  // split q/k
                    if (col < 32)
                        *(uint32_t*)&((__nv_bfloat16*)Yv)[(size_t)r * DD + col] = pack_bf16(c0, c1);
                    else
                        *(uint32_t*)&((__nv_bfloat16*)Y2)[(size_t)r * DD + col - 32] = pack_bf16(c0, c1);
                }
            }
        }
    }
}

// ---------------------------------------------------------------------------
// Flash attention: bf16 mma, no online max, MUFU ex2, S-split across
// warp pairs with smem P exchange, row sums via ones-MMA, cp.async 2-buffer.
// ---------------------------------------------------------------------------
#define KSTRIDE 40    // 80 B
#define VSTRIDE 264   // 528 B
#define KBYTES  (64 * KSTRIDE * 2)   // 5120
#define VBYTES  (64 * VSTRIDE * 2)   // 33792
#define PSTRIDE 72    // P row stride (bf16): 64 + 8 pad -> 144 B
#define PBYTES  (16 * PSTRIDE * 2)   // 2304 per wm group
#define ONE2BF  0x3F803F80u

__global__ __launch_bounds__(256, 2) void attn_kernel(
    const __nv_bfloat16* __restrict__ gq, const __nv_bfloat16* __restrict__ gk,
    const __nv_bfloat16* __restrict__ gv, __nv_bfloat16* __restrict__ gatt)
{
    extern __shared__ char smraw[];
    char* sQ  = smraw;
    char* sK0 = sQ + KBYTES;
    char* sV0 = sK0 + KBYTES;
    char* sK1 = sV0 + VBYTES;
    char* sV1 = sK1 + KBYTES;
    char* sP  = sV1 + VBYTES;          // 4 * PBYTES

    const int tid  = threadIdx.x;
    const int lane = tid & 31;
    const int warp = tid >> 5;
    const int wm   = warp >> 1;        // 0..3 -> rows 16*wm
    const int wn   = warp & 1;         // 0..1 -> key half / V-col half

    const int b  = blockIdx.y;
    const int qt = blockIdx.x;

    const __nv_bfloat16* qb = gq + (size_t)b * NTOK * DD + (size_t)qt * 64 * DD;
    const __nv_bfloat16* kb = gk + (size_t)b * NTOK * DD;
    const __nv_bfloat16* vb = gv + (size_t)b * NTOK * CC;

    const uint32_t sQ_u = smem_u32(sQ);
    const uint32_t sK_u[2] = { smem_u32(sK0), smem_u32(sK1) };
    const uint32_t sV_u[2] = { smem_u32(sV0), smem_u32(sV1) };
    const uint32_t sP_u = smem_u32(sP) + wm * PBYTES;

    // stage Q
    {
        int r = tid >> 2, c8 = tid & 3;
        *(uint4*)(sQ + r * (KSTRIDE * 2) + c8 * 16) = *(const uint4*)(qb + (size_t)r * DD + c8 * 8);
    }
    // prologue K/V tile 0
    {
        int r = tid >> 2, c = tid & 3;
        cp_async16(sK_u[0] + r * (KSTRIDE * 2) + c * 16, kb + (size_t)r * DD + c * 8);
        #pragma unroll
        for (int i = 0; i < 8; i++) {
            int idx = tid + i * 256;
            int vr = idx >> 5, vc = idx & 31;
            cp_async16(sV_u[0] + vr * (VSTRIDE * 2) + vc * 16, vb + (size_t)vr * CC + vc * 8);
        }
    }
    cp_async_commit();
    __syncthreads();

    uint32_t qA[2][4];
    {
        uint32_t base = sQ_u + (16 * wm + (lane & 15)) * (KSTRIDE * 2) + ((lane >> 4) & 1) * 16;
        ldsm_x4(qA[0][0], qA[0][1], qA[0][2], qA[0][3], base);
        ldsm_x4(qA[1][0], qA[1][1], qA[1][2], qA[1][3], base + 32);
    }

    float acc[16][4];
    #pragma unroll
    for (int j = 0; j < 16; j++)
        #pragma unroll
        for (int q4 = 0; q4 < 4; q4++) acc[j][q4] = 0.0f;
    float acc_ones[4] = {0.0f, 0.0f, 0.0f, 0.0f};

    const int krow4  = ((lane >> 4) & 1) * 8 + (lane & 7);
    const int kcolb4 = ((lane >> 3) & 1) * 16;
    const int vrow4  = (lane & 7) + ((lane >> 3) & 1) * 8;
    const int vcolb4 = ((lane >> 4) & 1) * 16;

    for (int kt = 0; kt < NTOK / 64; kt++) {
        cp_async_wait0();
        __syncthreads();

        if (kt + 1 < NTOK / 64) {
            int nb = (kt + 1) & 1;
            const __nv_bfloat16* kbt = kb + (size_t)(kt + 1) * 64 * DD;
            const __nv_bfloat16* vbt = vb + (size_t)(kt + 1) * 64 * CC;
            int r = tid >> 2, c = tid & 3;
            cp_async16(sK_u[nb] + r * (KSTRIDE * 2) + c * 16, kbt + (size_t)r * DD + c * 8);
            #pragma unroll
            for (int i = 0; i < 8; i++) {
                int idx = tid + i * 256;
                int vr = idx >> 5, vc = idx & 31;
                cp_async16(sV_u[nb] + vr * (VSTRIDE * 2) + vc * 16, vbt + (size_t)vr * CC + vc * 8);
            }
        }
        cp_async_commit();

        const uint32_t sKb = sK_u[kt & 1];
        const uint32_t sVb = sV_u[kt & 1];

        // ---- S = Q @ K^T for this warp's 32-key half ----
        float sfrag[4][4];
        #pragma unroll
        for (int nt = 0; nt < 4; nt++)
            #pragma unroll
            for (int q4 = 0; q4 < 4; q4++) sfrag[nt][q4] = 0.0f;

        #pragma unroll
        for (int kbk = 0; kbk < 2; kbk++) {
            #pragma unroll
            for (int nt2 = 0; nt2 < 2; nt2++) {
                uint32_t b0, b1, b2, b3;
                ldsm_x4(b0, b1, b2, b3,
                        sKb + (wn * 32 + nt2 * 16 + krow4) * (KSTRIDE * 2) + kbk * 32 + kcolb4);
                mma_bf16(sfrag[2 * nt2],     qA[kbk][0], qA[kbk][1], qA[kbk][2], qA[kbk][3], b0, b1);
                mma_bf16(sfrag[2 * nt2 + 1], qA[kbk][0], qA[kbk][1], qA[kbk][2], qA[kbk][3], b2, b3);
            }
        }

        // ---- P = exp2(S) via MUFU EX2, store bf16 P to smem ----
        {
            uint32_t prow = lane >> 2;
            uint32_t pbase = sP_u + prow * (PSTRIDE * 2) + (wn * 32 + (lane & 3) * 2) * 2;
            #pragma unroll
            for (int nt = 0; nt < 4; nt++) {
                uint32_t pb_lo = pack_bf16(ex2_fast(sfrag[nt][0]), ex2_fast(sfrag[nt][1]));
                uint32_t pb_hi = pack_bf16(ex2_fast(sfrag[nt][2]), ex2_fast(sfrag[nt][3]));
                uint32_t a0 = pbase + nt * 16;
                asm volatile("st.shared.b32 [%0], %1;" :: "r"(a0), "r"(pb_lo) : "memory");
                asm volatile("st.shared.b32 [%0], %1;" :: "r"(a0 + 8 * (PSTRIDE * 2)), "r"(pb_hi) : "memory");
            }
        }
        asm volatile("bar.sync %0, %1;" :: "r"(wm + 1), "r"(64) : "memory");

        // ---- O += P @ V (full 64 keys; P from smem) + ones-MMA row sums ----
        #pragma unroll
        for (int kb2 = 0; kb2 < 4; kb2++) {
            uint32_t a0, a1, a2, a3;
            ldsm_x4(a0, a1, a2, a3,
                    sP_u + (lane & 15) * (PSTRIDE * 2) + kb2 * 32 + ((lane >> 4) & 1) * 16);
            mma_bf16(acc_ones, a0, a1, a2, a3, ONE2BF, ONE2BF);
            #pragma unroll
            for (int j2 = 0; j2 < 8; j2++) {
                uint32_t b0, b1, b2, b3;
                ldsm_x4_trans(b0, b1, b2, b3,
                              sVb + (kb2 * 16 + vrow4) * (VSTRIDE * 2) + wn * 256 + j2 * 32 + vcolb4);
                mma_bf16(acc[2 * j2],     a0, a1, a2, a3, b0, b1);
                mma_bf16(acc[2 * j2 + 1], a0, a1, a2, a3, b2, b3);
            }
        }
    }

    // epilogue: acc_ones[0]/[2] hold full row sums for rows r0 / r0+8
    float inv0 = 1.0f / acc_ones[0];
    float inv1 = 1.0f / acc_ones[2];

    __nv_bfloat16* ob = gatt + (size_t)b * NTOK * CC + (size_t)qt * 64 * CC;
    int row0 = 16 * wm + (lane >> 2);
    int colb = wn * 128 + (lane & 3) * 2;
    #pragma unroll
    for (int j = 0; j < 16; j++) {
        int col = colb + j * 8;
        *(uint32_t*)&ob[(size_t)row0 * CC + col]       = pack_bf16(acc[j][0] * inv0, acc[j][1] * inv0);
        *(uint32_t*)&ob[(size_t)(row0 + 8) * CC + col] = pack_bf16(acc[j][2] * inv1, acc[j][3] * inv1);
    }
}

// ---------------------------------------------------------------------------
extern "C" void kernel_launch(void* const* d_in, const int* in_sizes, int n_in,
                              void* d_out, int out_size)
{
    const float* x  = (const float*)d_in[0];
    const float* wq = (const float*)d_in[1];
    const float* bq = (const float*)d_in[2];
    const float* wk = (const float*)d_in[3];
    const float* bk = (const float*)d_in[4];
    const float* wv = (const float*)d_in[5];
    const float* bv = (const float*)d_in[6];
    const float* wo = (const float*)d_in[7];
    const float* bo = (const float*)d_in[8];
    float* out = (float*)d_out;

    __nv_bfloat16 *xb, *q, *k, *v, *att, *wqkb, *wvb, *wob;
    float* bqk;
    cudaGetSymbolAddress((void**)&xb,   g_xb);
    cudaGetSymbolAddress((void**)&q,    g_q);
    cudaGetSymbolAddress((void**)&k,    g_k);
    cudaGetSymbolAddress((void**)&v,    g_v);
    cudaGetSymbolAddress((void**)&att,  g_att);
    cudaGetSymbolAddress((void**)&wqkb, g_wqkb);
    cudaGetSymbolAddress((void**)&wvb,  g_wvb);
    cudaGetSymbolAddress((void**)&wob,  g_wob);
    cudaGetSymbolAddress((void**)&bqk,  g_bqk);

    dim3 blk(256);
    const float qscale = 1.4426950408889634f / 5.656854249492380f;  // log2(e)/sqrt(32)

    convert_x_kernel<<<MM * CC / 4 / 256, blk>>>((const float4*)x, (uint2*)xb);
    convert_w_kernel<<<CC * CC / 256, blk>>>(wq, bq, wk, bk, wv, wo, qscale);

    // fused Q|K projection, then V projection
    tc_gemm_kernel<64, 2><<<dim3(1, MM / 128), blk>>>(xb, wqkb, bqk, nullptr, q, k, 64);
    tc_gemm_kernel<128, 0><<<dim3(2, MM / 128), blk>>>(xb, wvb, bv, nullptr, v, nullptr, CC);

    // attention
    size_t smem = KBYTES + 2 * (KBYTES + VBYTES) + 4 * PBYTES;   // 92160 B
    cudaFuncSetAttribute(attn_kernel, cudaFuncAttributeMaxDynamicSharedMemorySize, (int)smem);
    attn_kernel<<<dim3(NTOK / 64, BB), blk, smem>>>(q, k, v, att);

    // output projection + bias + residual
    tc_gemm_kernel<128, 1><<<dim3(2, MM / 128), blk>>>(att, wob, bo, x, out, nullptr, CC);
}

// round 8
// speedup vs baseline: 7.3069x; 1.0025x over previous
#include <cuda_runtime.h>
#include <cuda_bf16.h>
#include <math.h>
#include <stdint.h>

#define BB   4
#define NTOK 4096
#define CC   256
#define DD   32
#define MM   (BB * NTOK)   // 16384

// Scratch (allocation-free per harness rules)
__device__ __nv_bfloat16 g_xb[MM * CC];
__device__ __nv_bfloat16 g_q[MM * DD];
__device__ __nv_bfloat16 g_k[MM * DD];
__device__ __nv_bfloat16 g_v[MM * CC];
__device__ __nv_bfloat16 g_att[MM * CC];
__device__ __nv_bfloat16 g_wqkb[CC * 64];   // cols 0-31 wq*qscale, 32-63 wk
__device__ __nv_bfloat16 g_wvb[CC * CC];
__device__ __nv_bfloat16 g_wob[CC * CC];
__device__ float         g_bqk[64];

// ---------------------------------------------------------------------------
// PTX helpers
// ---------------------------------------------------------------------------
__device__ __forceinline__ uint32_t smem_u32(const void* p) {
    return (uint32_t)__cvta_generic_to_shared(p);
}
__device__ __forceinline__ void ldsm_x4(uint32_t& r0, uint32_t& r1, uint32_t& r2, uint32_t& r3, uint32_t addr) {
    asm volatile("ldmatrix.sync.aligned.m8n8.x4.shared.b16 {%0,%1,%2,%3}, [%4];\n"
                 : "=r"(r0), "=r"(r1), "=r"(r2), "=r"(r3) : "r"(addr));
}
__device__ __forceinline__ void ldsm_x4_trans(uint32_t& r0, uint32_t& r1, uint32_t& r2, uint32_t& r3, uint32_t addr) {
    asm volatile("ldmatrix.sync.aligned.m8n8.x4.trans.shared.b16 {%0,%1,%2,%3}, [%4];\n"
                 : "=r"(r0), "=r"(r1), "=r"(r2), "=r"(r3) : "r"(addr));
}
__device__ __forceinline__ void mma_bf16(float* c, uint32_t a0, uint32_t a1, uint32_t a2, uint32_t a3,
                                         uint32_t b0, uint32_t b1) {
    asm volatile(
        "mma.sync.aligned.m16n8k16.row.col.f32.bf16.bf16.f32 "
        "{%0,%1,%2,%3}, {%4,%5,%6,%7}, {%8,%9}, {%0,%1,%2,%3};\n"
        : "+f"(c[0]), "+f"(c[1]), "+f"(c[2]), "+f"(c[3])
        : "r"(a0), "r"(a1), "r"(a2), "r"(a3), "r"(b0), "r"(b1));
}
__device__ __forceinline__ void cp_async16(uint32_t smem_dst, const void* gsrc) {
    asm volatile("cp.async.cg.shared.global [%0], [%1], 16;\n" :: "r"(smem_dst), "l"(gsrc));
}
__device__ __forceinline__ void cp_async_commit() { asm volatile("cp.async.commit_group;\n"); }
__device__ __forceinline__ void cp_async_wait1()  { asm volatile("cp.async.wait_group 1;\n"); }
__device__ __forceinline__ void cp_async_wait2()  { asm volatile("cp.async.wait_group 2;\n"); }

__device__ __forceinline__ uint32_t pack_bf16(float lo, float hi) {
    uint32_t r;
    asm("cvt.rn.bf16x2.f32 %0, %1, %2;" : "=r"(r) : "f"(hi), "f"(lo));
    return r;
}
__device__ __forceinline__ float ex2_fast(float x) {
    float y;
    asm("ex2.approx.ftz.f32 %0, %1;" : "=f"(y) : "f"(x));
    return y;
}

// ---------------------------------------------------------------------------
// fp32 -> bf16 conversion kernels
// ---------------------------------------------------------------------------
__global__ __launch_bounds__(256) void convert_x_kernel(const float4* __restrict__ x, uint2* __restrict__ o) {
    int i = blockIdx.x * 256 + threadIdx.x;
    float4 v = x[i];
    o[i] = make_uint2(pack_bf16(v.x, v.y), pack_bf16(v.z, v.w));
}
__global__ __launch_bounds__(256) void convert_w_kernel(
    const float* __restrict__ wq, const float* __restrict__ bq,
    const float* __restrict__ wk, const float* __restrict__ bk,
    const float* __restrict__ wv, const float* __restrict__ wo, float qscale)
{
    int i = blockIdx.x * 256 + threadIdx.x;
    if (i < CC * CC) {
        g_wvb[i] = __float2bfloat16(wv[i]);
        g_wob[i] = __float2bfloat16(wo[i]);
    }
    if (i < CC * 64) {
        int r = i >> 6, c = i & 63;
        g_wqkb[i] = (c < 32) ? __float2bfloat16(wq[r * DD + c] * qscale)
                             : __float2bfloat16(wk[r * DD + c - 32]);
    }
    if (i < 64) g_bqk[i] = (i < 32) ? bq[i] * qscale : bk[i - 32];
}

// ---------------------------------------------------------------------------
// bf16 tensor-core GEMM, 4-stage cp.async pipeline (dynamic smem).
// MODE: 0 = bf16 out, 1 = fp32 out + resid, 2 = split Q/K bf16 out.
// ---------------------------------------------------------------------------
#define GXS 40   // A tile row stride (bf16)
#define GEMM_A_STAGE (128 * GXS * 2)   // 10240 B

template <int CTA_N, int MODE>
__global__ __launch_bounds__(256, 2) void tc_gemm_kernel(
    const __nv_bfloat16* __restrict__ A, const __nv_bfloat16* __restrict__ W,
    const float* __restrict__ bias, const float* __restrict__ resid,
    void* __restrict__ Yv, void* __restrict__ Y2, int N)
{
    constexpr int WS = CTA_N + 8;
    constexpr int NW = CTA_N / 8;
    constexpr int MW = 2;
    constexpr int NB = (CTA_N == 128) ? 8 : 4;
    constexpr int W_STAGE = 32 * WS * 2;

    extern __shared__ char gsm[];
    const uint32_t base = smem_u32(gsm);

    const int tid  = threadIdx.x;
    const int lane = tid & 31;
    const int warp = tid >> 5;
    const int wm   = warp >> 1;
    const int wn   = warp & 1;
    const int row0 = blockIdx.y * 128;
    const int n0   = blockIdx.x * CTA_N;

    auto sA_u = [&](int s) { return base + s * GEMM_A_STAGE; };
    auto sW_u = [&](int s) { return base + 4 * GEMM_A_STAGE + s * W_STAGE; };

    auto load_chunk = [&](int buf, int k0) {
        #pragma unroll
        for (int i = 0; i < 2; i++) {
            int idx = tid + i * 256;
            int r = idx >> 2, c = idx & 3;
            cp_async16(sA_u(buf) + r * (GXS * 2) + c * 16,
                       A + (size_t)(row0 + r) * CC + k0 + c * 8);
        }
        #pragma unroll
        for (int i = 0; i < (32 * NW + 255) / 256; i++) {
            int idx = tid + i * 256;
            int r = idx / NW, c = idx % NW;
            cp_async16(sW_u(buf) + r * (WS * 2) + c * 16,
                       W + (size_t)(k0 + r) * N + n0 + c * 8);
        }
        cp_async_commit();
    };

    load_chunk(0, 0);
    load_chunk(1, 32);
    load_chunk(2, 64);

    float acc[MW][NB][4];
    #pragma unroll
    for (int m = 0; m < MW; m++)
        #pragma unroll
        for (int nb = 0; nb < NB; nb++)
            #pragma unroll
            for (int q = 0; q < 4; q++) acc[m][nb][q] = 0.0f;

    const int arow = (lane & 15);
    const int acolb = ((lane >> 4) & 1) * 16;
    const int brow = (lane & 7) + ((lane >> 3) & 1) * 8;
    const int bcolb = ((lane >> 4) & 1) * 16;

    for (int ch = 0; ch < 8; ch++) {
        cp_async_wait2();
        __syncthreads();
        if (ch + 3 < 8) load_chunk((ch + 3) & 3, (ch + 3) * 32);
        else cp_async_commit();

        const uint32_t sAb = sA_u(ch & 3);
        const uint32_t sWb = sW_u(ch & 3);

        #pragma unroll
        for (int kk = 0; kk < 2; kk++) {
            uint32_t a[MW][4];
            #pragma unroll
            for (int m = 0; m < MW; m++)
                ldsm_x4(a[m][0], a[m][1], a[m][2], a[m][3],
                        sAb + (wm * (MW * 16) + m * 16 + arow) * (GXS * 2) + kk * 32 + acolb);
            #pragma unroll
            for (int nb2 = 0; nb2 < NB / 2; nb2++) {
                uint32_t b0, b1, b2, b3;
                ldsm_x4_trans(b0, b1, b2, b3,
                              sWb + (kk * 16 + brow) * (WS * 2) + (wn * (NB * 8) + nb2 * 16) * 2 + bcolb);
                #pragma unroll
                for (int m = 0; m < MW; m++) {
                    mma_bf16(acc[m][2 * nb2],     a[m][0], a[m][1], a[m][2], a[m][3], b0, b1);
                    mma_bf16(acc[m][2 * nb2 + 1], a[m][0], a[m][1], a[m][2], a[m][3], b2, b3);
                }
            }
        }
    }

    #pragma unroll
    for (int m = 0; m < MW; m++) {
        int r0 = row0 + wm * (MW * 16) + m * 16 + (lane >> 2);
        #pragma unroll
        for (int nb = 0; nb < NB; nb++) {
            int col = n0 + wn * (NB * 8) + nb * 8 + (lane & 3) * 2;
            #pragma unroll
            for (int h = 0; h < 2; h++) {
                int r = r0 + h * 8;
                float c0 = acc[m][nb][2 * h]     + bias[col];
                float c1 = acc[m][nb][2 * h + 1] + bias[col + 1];
                if (MODE == 1) {
                    float2 rr = *(const float2*)&resid[(size_t)r * N + col];
                    *(float2*)&((float*)Yv)[(size_t)r * N + col] = make_float2(c0 + rr.x, c1 + rr.y);
                } else if (MODE == 0) {
                    *(uint32_t*)&((__nv_bfloat16*)Yv)[(size_t)r * N + col] = pack_bf16(c0, c1);
                } else {
                    if (col < 32)
                        *(uint32_t*)&((__nv_bfloat16*)Yv)[(size_t)r * DD + col] = pack_bf16(c0, c1);
                    else
                        *(uint32_t*)&((__nv_bfloat16*)Y2)[(size_t)r * DD + col - 32] = pack_bf16(c0, c1);
                }
            }
        }
    }
}

// ---------------------------------------------------------------------------
// Flash attention, PV-lagged pipeline.
// CTA = 512 threads, 128 queries. 4-buffered K/V (64-key tiles), 2-buffered P.
// Per iter kt: wait; sync; prefetch(kt+2); PV(kt-1); S(kt); exp; STS P; bar.
// wm = warp>>1 (0..7): rows 16*wm. wn = warp&1: key-half for S, V-col-half.
// Row sums via ones-MMA during PV.
// ---------------------------------------------------------------------------
#define KSTRIDE 40    // 80 B
#define VSTRIDE 264   // 528 B
#define A_KB    (64 * KSTRIDE * 2)    // 5120
#define A_VB    (64 * VSTRIDE * 2)    // 33792
#define PSTRIDE 72
#define PGRP    (16 * PSTRIDE * 2)    // 2304 per wm group
#define PBUF    (8 * PGRP)            // 18432 per buffer
#define AT_SQ   0
#define AT_SK   (128 * KSTRIDE * 2)                // 10240
#define AT_SV   (AT_SK + 4 * A_KB)                 // 30720
#define AT_SP   (AT_SV + 4 * A_VB)                 // 165888
#define AT_TOT  (AT_SP + 2 * PBUF)                 // 202752
#define ONE2BF  0x3F803F80u

__global__ __launch_bounds__(512, 1) void attn_kernel(
    const __nv_bfloat16* __restrict__ gq, const __nv_bfloat16* __restrict__ gk,
    const __nv_bfloat16* __restrict__ gv, __nv_bfloat16* __restrict__ gatt)
{
    extern __shared__ char sm[];
    const uint32_t smb = smem_u32(sm);

    const int tid  = threadIdx.x;
    const int lane = tid & 31;
    const int warp = tid >> 5;
    const int wm   = warp >> 1;        // 0..7
    const int wn   = warp & 1;

    const int b  = blockIdx.y;
    const int qt = blockIdx.x;

    const __nv_bfloat16* qb = gq + ((size_t)b * NTOK + qt * 128) * DD;
    const __nv_bfloat16* kb = gk + (size_t)b * NTOK * DD;
    const __nv_bfloat16* vb = gv + (size_t)b * NTOK * CC;

    auto sK_u = [&](int s) { return smb + AT_SK + s * A_KB; };
    auto sV_u = [&](int s) { return smb + AT_SV + s * A_VB; };
    auto sP_u = [&](int p) { return smb + AT_SP + p * PBUF + wm * PGRP; };

    auto load_tile = [&](int t, int s) {
        if (tid < 256) {
            int r = tid >> 2, c = tid & 3;
            cp_async16(sK_u(s) + r * (KSTRIDE * 2) + c * 16,
                       kb + ((size_t)t * 64 + r) * DD + c * 8);
        }
        #pragma unroll
        for (int i = 0; i < 4; i++) {
            int idx = tid + i * 512;
            int vr = idx >> 5, vc = idx & 31;
            cp_async16(sV_u(s) + vr * (VSTRIDE * 2) + vc * 16,
                       vb + ((size_t)t * 64 + vr) * CC + vc * 8);
        }
    };

    // stage Q (128x32 bf16)
    {
        int r = tid >> 2, c = tid & 3;
        *(uint4*)(sm + AT_SQ + r * (KSTRIDE * 2) + c * 16) =
            *(const uint4*)(qb + (size_t)r * DD + c * 8);
    }
    load_tile(0, 0); cp_async_commit();
    load_tile(1, 1); cp_async_commit();
    __syncthreads();

    uint32_t qA[2][4];
    {
        uint32_t base = smb + AT_SQ + (16 * wm + (lane & 15)) * (KSTRIDE * 2) + ((lane >> 4) & 1) * 16;
        ldsm_x4(qA[0][0], qA[0][1], qA[0][2], qA[0][3], base);
        ldsm_x4(qA[1][0], qA[1][1], qA[1][2], qA[1][3], base + 32);
    }

    float acc[16][4];
    #pragma unroll
    for (int j = 0; j < 16; j++)
        #pragma unroll
        for (int q4 = 0; q4 < 4; q4++) acc[j][q4] = 0.0f;
    float acc_ones[4] = {0.0f, 0.0f, 0.0f, 0.0f};

    const int krow4  = ((lane >> 4) & 1) * 8 + (lane & 7);
    const int kcolb4 = ((lane >> 3) & 1) * 16;
    const int vrow4  = (lane & 7) + ((lane >> 3) & 1) * 8;
    const int vcolb4 = ((lane >> 4) & 1) * 16;
    const uint32_t pread_off  = (lane & 15) * (PSTRIDE * 2) + ((lane >> 4) & 1) * 16;
    const uint32_t pwrite_off = (lane >> 2) * (PSTRIDE * 2) + (wn * 32 + (lane & 3) * 2) * 2;

    auto do_pv = [&](int j) {
        const uint32_t sVb = sV_u(j & 3);
        const uint32_t sPb = sP_u(j & 1);
        #pragma unroll
        for (int kb2 = 0; kb2 < 4; kb2++) {
            uint32_t a0, a1, a2, a3;
            ldsm_x4(a0, a1, a2, a3, sPb + pread_off + kb2 * 32);
            mma_bf16(acc_ones, a0, a1, a2, a3, ONE2BF, ONE2BF);
            #pragma unroll
            for (int j2 = 0; j2 < 8; j2++) {
                uint32_t b0, b1, b2, b3;
                ldsm_x4_trans(b0, b1, b2, b3,
                              sVb + (kb2 * 16 + vrow4) * (VSTRIDE * 2) + wn * 256 + j2 * 32 + vcolb4);
                mma_bf16(acc[2 * j2],     a0, a1, a2, a3, b0, b1);
                mma_bf16(acc[2 * j2 + 1], a0, a1, a2, a3, b2, b3);
            }
        }
    };

    for (int kt = 0; kt < 64; kt++) {
        cp_async_wait1();          // tile kt resident
        __syncthreads();           // visible to all; V(kt-2) slot free
        if (kt + 2 < 64) load_tile(kt + 2, (kt + 2) & 3);
        cp_async_commit();

        if (kt > 0) do_pv(kt - 1);

        // ---- S = Q @ K^T for this warp's 32-key half ----
        const uint32_t sKb = sK_u(kt & 3);
        float sfrag[4][4];
        #pragma unroll
        for (int nt = 0; nt < 4; nt++)
            #pragma unroll
            for (int q4 = 0; q4 < 4; q4++) sfrag[nt][q4] = 0.0f;
        #pragma unroll
        for (int kbk = 0; kbk < 2; kbk++) {
            #pragma unroll
            for (int nt2 = 0; nt2 < 2; nt2++) {
                uint32_t b0, b1, b2, b3;
                ldsm_x4(b0, b1, b2, b3,
                        sKb + (wn * 32 + nt2 * 16 + krow4) * (KSTRIDE * 2) + kbk * 32 + kcolb4);
                mma_bf16(sfrag[2 * nt2],     qA[kbk][0], qA[kbk][1], qA[kbk][2], qA[kbk][3], b0, b1);
                mma_bf16(sfrag[2 * nt2 + 1], qA[kbk][0], qA[kbk][1], qA[kbk][2], qA[kbk][3], b2, b3);
            }
        }

        // ---- P = exp2(S) -> smem P[kt&1] ----
        {
            uint32_t pbase = sP_u(kt & 1) + pwrite_off;
            #pragma unroll
            for (int nt = 0; nt < 4; nt++) {
                uint32_t pb_lo = pack_bf16(ex2_fast(sfrag[nt][0]), ex2_fast(sfrag[nt][1]));
                uint32_t pb_hi = pack_bf16(ex2_fast(sfrag[nt][2]), ex2_fast(sfrag[nt][3]));
                uint32_t a0 = pbase + nt * 16;
                asm volatile("st.shared.b32 [%0], %1;" :: "r"(a0), "r"(pb_lo) : "memory");
                asm volatile("st.shared.b32 [%0], %1;" :: "r"(a0 + 8 * (PSTRIDE * 2)), "r"(pb_hi) : "memory");
            }
        }
        asm volatile("bar.sync %0, %1;" :: "r"(wm + 1), "r"(64) : "memory");
    }

    do_pv(63);

    // epilogue: acc_ones[0]/[2] = row sums for rows r0 / r0+8
    float inv0 = 1.0f / acc_ones[0];
    float inv1 = 1.0f / acc_ones[2];

    __nv_bfloat16* ob = gatt + ((size_t)b * NTOK + qt * 128) * CC;
    int row0 = 16 * wm + (lane >> 2);
    int colb = wn * 128 + (lane & 3) * 2;
    #pragma unroll
    for (int j = 0; j < 16; j++) {
        int col = colb + j * 8;
        *(uint32_t*)&ob[(size_t)row0 * CC + col]       = pack_bf16(acc[j][0] * inv0, acc[j][1] * inv0);
        *(uint32_t*)&ob[(size_t)(row0 + 8) * CC + col] = pack_bf16(acc[j][2] * inv1, acc[j][3] * inv1);
    }
}

// ---------------------------------------------------------------------------
extern "C" void kernel_launch(void* const* d_in, const int* in_sizes, int n_in,
                              void* d_out, int out_size)
{
    const float* x  = (const float*)d_in[0];
    const float* wq = (const float*)d_in[1];
    const float* bq = (const float*)d_in[2];
    const float* wk = (const float*)d_in[3];
    const float* bk = (const float*)d_in[4];
    const float* wv = (const float*)d_in[5];
    const float* bv = (const float*)d_in[6];
    const float* wo = (const float*)d_in[7];
    const float* bo = (const float*)d_in[8];
    float* out = (float*)d_out;

    __nv_bfloat16 *xb, *q, *k, *v, *att, *wqkb, *wvb, *wob;
    float* bqk;
    cudaGetSymbolAddress((void**)&xb,   g_xb);
    cudaGetSymbolAddress((void**)&q,    g_q);
    cudaGetSymbolAddress((void**)&k,    g_k);
    cudaGetSymbolAddress((void**)&v,    g_v);
    cudaGetSymbolAddress((void**)&att,  g_att);
    cudaGetSymbolAddress((void**)&wqkb, g_wqkb);
    cudaGetSymbolAddress((void**)&wvb,  g_wvb);
    cudaGetSymbolAddress((void**)&wob,  g_wob);
    cudaGetSymbolAddress((void**)&bqk,  g_bqk);

    dim3 blk(256);
    const float qscale = 1.4426950408889634f / 5.656854249492380f;  // log2(e)/sqrt(32)

    convert_x_kernel<<<MM * CC / 4 / 256, blk>>>((const float4*)x, (uint2*)xb);
    convert_w_kernel<<<CC * CC / 256, blk>>>(wq, bq, wk, bk, wv, wo, qscale);

    const int smem64  = 4 * GEMM_A_STAGE + 4 * 32 * (64 + 8) * 2;    // 59392
    const int smem128 = 4 * GEMM_A_STAGE + 4 * 32 * (128 + 8) * 2;   // 75776
    cudaFuncSetAttribute(tc_gemm_kernel<64, 2>,  cudaFuncAttributeMaxDynamicSharedMemorySize, smem64);
    cudaFuncSetAttribute(tc_gemm_kernel<128, 0>, cudaFuncAttributeMaxDynamicSharedMemorySize, smem128);
    cudaFuncSetAttribute(tc_gemm_kernel<128, 1>, cudaFuncAttributeMaxDynamicSharedMemorySize, smem128);

    // fused Q|K projection, then V projection
    tc_gemm_kernel<64, 2><<<dim3(1, MM / 128), blk, smem64>>>(xb, wqkb, bqk, nullptr, q, k, 64);
    tc_gemm_kernel<128, 0><<<dim3(2, MM / 128), blk, smem128>>>(xb, wvb, bv, nullptr, v, nullptr, CC);

    // attention (512 threads, 128 queries/CTA)
    cudaFuncSetAttribute(attn_kernel, cudaFuncAttributeMaxDynamicSharedMemorySize, AT_TOT);
    attn_kernel<<<dim3(NTOK / 128, BB), 512, AT_TOT>>>(q, k, v, att);

    // output projection + bias + residual
    tc_gemm_kernel<128, 1><<<dim3(2, MM / 128), blk, smem128>>>(att, wob, bo, x, out, nullptr, CC);
}

// round 9
// speedup vs baseline: 7.4632x; 1.0214x over previous
#include <cuda_runtime.h>
#include <cuda_bf16.h>
#include <math.h>
#include <stdint.h>

#define BB   4
#define NTOK 4096
#define CC   256
#define DD   32
#define MM   (BB * NTOK)   // 16384

// Scratch (allocation-free per harness rules)
__device__ __nv_bfloat16 g_xb[MM * CC];
__device__ __nv_bfloat16 g_q[MM * DD];
__device__ __nv_bfloat16 g_k[MM * DD];
__device__ __nv_bfloat16 g_v[MM * CC];
__device__ __nv_bfloat16 g_att[MM * CC];
__device__ __nv_bfloat16 g_wqkb[CC * 64];   // cols 0-31 wq*qscale, 32-63 wk
__device__ __nv_bfloat16 g_wvb[CC * CC];
__device__ __nv_bfloat16 g_wob[CC * CC];
__device__ float         g_bqk[64];

// ---------------------------------------------------------------------------
// PTX helpers
// ---------------------------------------------------------------------------
__device__ __forceinline__ uint32_t smem_u32(const void* p) {
    return (uint32_t)__cvta_generic_to_shared(p);
}
__device__ __forceinline__ void ldsm_x4(uint32_t& r0, uint32_t& r1, uint32_t& r2, uint32_t& r3, uint32_t addr) {
    asm volatile("ldmatrix.sync.aligned.m8n8.x4.shared.b16 {%0,%1,%2,%3}, [%4];\n"
                 : "=r"(r0), "=r"(r1), "=r"(r2), "=r"(r3) : "r"(addr));
}
__device__ __forceinline__ void ldsm_x4_trans(uint32_t& r0, uint32_t& r1, uint32_t& r2, uint32_t& r3, uint32_t addr) {
    asm volatile("ldmatrix.sync.aligned.m8n8.x4.trans.shared.b16 {%0,%1,%2,%3}, [%4];\n"
                 : "=r"(r0), "=r"(r1), "=r"(r2), "=r"(r3) : "r"(addr));
}
__device__ __forceinline__ void mma_bf16(float* c, uint32_t a0, uint32_t a1, uint32_t a2, uint32_t a3,
                                         uint32_t b0, uint32_t b1) {
    asm volatile(
        "mma.sync.aligned.m16n8k16.row.col.f32.bf16.bf16.f32 "
        "{%0,%1,%2,%3}, {%4,%5,%6,%7}, {%8,%9}, {%0,%1,%2,%3};\n"
        : "+f"(c[0]), "+f"(c[1]), "+f"(c[2]), "+f"(c[3])
        : "r"(a0), "r"(a1), "r"(a2), "r"(a3), "r"(b0), "r"(b1));
}
__device__ __forceinline__ void cp_async16(uint32_t smem_dst, const void* gsrc) {
    asm volatile("cp.async.cg.shared.global [%0], [%1], 16;\n" :: "r"(smem_dst), "l"(gsrc));
}
__device__ __forceinline__ void cp_async_commit() { asm volatile("cp.async.commit_group;\n"); }
__device__ __forceinline__ void cp_async_wait1()  { asm volatile("cp.async.wait_group 1;\n"); }
__device__ __forceinline__ void cp_async_wait2()  { asm volatile("cp.async.wait_group 2;\n"); }

__device__ __forceinline__ uint32_t pack_bf16(float lo, float hi) {
    uint32_t r;
    asm("cvt.rn.bf16x2.f32 %0, %1, %2;" : "=r"(r) : "f"(hi), "f"(lo));
    return r;
}
__device__ __forceinline__ float ex2_fast(float x) {
    float y;
    asm("ex2.approx.ftz.f32 %0, %1;" : "=f"(y) : "f"(x));
    return y;
}

// ---------------------------------------------------------------------------
// merged fp32 -> bf16 conversion (x + all weights)
// ---------------------------------------------------------------------------
__global__ __launch_bounds__(256) void convert_all_kernel(
    const float4* __restrict__ x,
    const float* __restrict__ wq, const float* __restrict__ bq,
    const float* __restrict__ wk, const float* __restrict__ bk,
    const float* __restrict__ wv, const float* __restrict__ wo, float qscale)
{
    int i = blockIdx.x * 256 + threadIdx.x;
    float4 v = x[i];
    ((uint2*)g_xb)[i] = make_uint2(pack_bf16(v.x, v.y), pack_bf16(v.z, v.w));

    if (i < CC * CC) {
        g_wvb[i] = __float2bfloat16(wv[i]);
        g_wob[i] = __float2bfloat16(wo[i]);
    }
    if (i < CC * 64) {
        int r = i >> 6, c = i & 63;
        g_wqkb[i] = (c < 32) ? __float2bfloat16(wq[r * DD + c] * qscale)
                             : __float2bfloat16(wk[r * DD + c - 32]);
    }
    if (i < 64) g_bqk[i] = (i < 32) ? bq[i] * qscale : bk[i - 32];
}

// ---------------------------------------------------------------------------
// bf16 tensor-core GEMM, 4-stage cp.async pipeline (dynamic smem).
// MODE: 0 = bf16 out, 1 = fp32 out + resid, 2 = split Q/K bf16 out.
// ---------------------------------------------------------------------------
#define GXS 40   // A tile row stride (bf16)
#define GEMM_A_STAGE (128 * GXS * 2)   // 10240 B

template <int CTA_N, int MODE>
__global__ __launch_bounds__(256, 2) void tc_gemm_kernel(
    const __nv_bfloat16* __restrict__ A, const __nv_bfloat16* __restrict__ W,
    const float* __restrict__ bias, const float* __restrict__ resid,
    void* __restrict__ Yv, void* __restrict__ Y2, int N)
{
    constexpr int WS = CTA_N + 8;
    constexpr int NW = CTA_N / 8;
    constexpr int MW = 2;
    constexpr int NB = (CTA_N == 128) ? 8 : 4;
    constexpr int W_STAGE = 32 * WS * 2;

    extern __shared__ char gsm[];
    const uint32_t base = smem_u32(gsm);

    const int tid  = threadIdx.x;
    const int lane = tid & 31;
    const int warp = tid >> 5;
    const int wm   = warp >> 1;
    const int wn   = warp & 1;
    const int row0 = blockIdx.y * 128;
    const int n0   = blockIdx.x * CTA_N;

    auto sA_u = [&](int s) { return base + s * GEMM_A_STAGE; };
    auto sW_u = [&](int s) { return base + 4 * GEMM_A_STAGE + s * W_STAGE; };

    auto load_chunk = [&](int buf, int k0) {
        #pragma unroll
        for (int i = 0; i < 2; i++) {
            int idx = tid + i * 256;
            int r = idx >> 2, c = idx & 3;
            cp_async16(sA_u(buf) + r * (GXS * 2) + c * 16,
                       A + (size_t)(row0 + r) * CC + k0 + c * 8);
        }
        #pragma unroll
        for (int i = 0; i < (32 * NW + 255) / 256; i++) {
            int idx = tid + i * 256;
            int r = idx / NW, c = idx % NW;
            cp_async16(sW_u(buf) + r * (WS * 2) + c * 16,
                       W + (size_t)(k0 + r) * N + n0 + c * 8);
        }
        cp_async_commit();
    };

    load_chunk(0, 0);
    load_chunk(1, 32);
    load_chunk(2, 64);

    float acc[MW][NB][4];
    #pragma unroll
    for (int m = 0; m < MW; m++)
        #pragma unroll
        for (int nb = 0; nb < NB; nb++)
            #pragma unroll
            for (int q = 0; q < 4; q++) acc[m][nb][q] = 0.0f;

    const int arow = (lane & 15);
    const int acolb = ((lane >> 4) & 1) * 16;
    const int brow = (lane & 7) + ((lane >> 3) & 1) * 8;
    const int bcolb = ((lane >> 4) & 1) * 16;

    for (int ch = 0; ch < 8; ch++) {
        cp_async_wait2();
        __syncthreads();
        if (ch + 3 < 8) load_chunk((ch + 3) & 3, (ch + 3) * 32);
        else cp_async_commit();

        const uint32_t sAb = sA_u(ch & 3);
        const uint32_t sWb = sW_u(ch & 3);

        #pragma unroll
        for (int kk = 0; kk < 2; kk++) {
            uint32_t a[MW][4];
            #pragma unroll
            for (int m = 0; m < MW; m++)
                ldsm_x4(a[m][0], a[m][1], a[m][2], a[m][3],
                        sAb + (wm * (MW * 16) + m * 16 + arow) * (GXS * 2) + kk * 32 + acolb);
            #pragma unroll
            for (int nb2 = 0; nb2 < NB / 2; nb2++) {
                uint32_t b0, b1, b2, b3;
                ldsm_x4_trans(b0, b1, b2, b3,
                              sWb + (kk * 16 + brow) * (WS * 2) + (wn * (NB * 8) + nb2 * 16) * 2 + bcolb);
                #pragma unroll
                for (int m = 0; m < MW; m++) {
                    mma_bf16(acc[m][2 * nb2],     a[m][0], a[m][1], a[m][2], a[m][3], b0, b1);
                    mma_bf16(acc[m][2 * nb2 + 1], a[m][0], a[m][1], a[m][2], a[m][3], b2, b3);
                }
            }
        }
    }

    #pragma unroll
    for (int m = 0; m < MW; m++) {
        int r0 = row0 + wm * (MW * 16) + m * 16 + (lane >> 2);
        #pragma unroll
        for (int nb = 0; nb < NB; nb++) {
            int col = n0 + wn * (NB * 8) + nb * 8 + (lane & 3) * 2;
            #pragma unroll
            for (int h = 0; h < 2; h++) {
                int r = r0 + h * 8;
                float c0 = acc[m][nb][2 * h]     + bias[col];
                float c1 = acc[m][nb][2 * h + 1] + bias[col + 1];
                if (MODE == 1) {
                    float2 rr = *(const float2*)&resid[(size_t)r * N + col];
                    *(float2*)&((float*)Yv)[(size_t)r * N + col] = make_float2(c0 + rr.x, c1 + rr.y);
                } else if (MODE == 0) {
                    *(uint32_t*)&((__nv_bfloat16*)Yv)[(size_t)r * N + col] = pack_bf16(c0, c1);
                } else {
                    if (col < 32)
                        *(uint32_t*)&((__nv_bfloat16*)Yv)[(size_t)r * DD + col] = pack_bf16(c0, c1);
                    else
                        *(uint32_t*)&((__nv_bfloat16*)Y2)[(size_t)r * DD + col - 32] = pack_bf16(c0, c1);
                }
            }
        }
    }
}

// ---------------------------------------------------------------------------
// Flash attention: 256 threads, 8 warps (4 wm x 2 wn), 32-row warp tiles.
// V/P fragments are reused across the warp's two 16-row m-blocks, halving
// LDSM traffic per MMA. 4-buffered K/V, double-buffered P, in-order
// S -> exp -> bar -> PV. Row sums via ones-MMA.
// ---------------------------------------------------------------------------
#define KSTRIDE 40    // 80 B
#define VSTRIDE 264   // 528 B
#define A_KB    (64 * KSTRIDE * 2)    // 5120
#define A_VB    (64 * VSTRIDE * 2)    // 33792
#define PSTRIDE 72                    // 144 B
#define PBUF    (128 * PSTRIDE * 2)   // 18432
#define AT_SQ   0
#define AT_SK   (128 * KSTRIDE * 2)                // 10240
#define AT_SV   (AT_SK + 4 * A_KB)                 // 30720
#define AT_SP   (AT_SV + 4 * A_VB)                 // 165888
#define AT_TOT  (AT_SP + 2 * PBUF)                 // 202752
#define ONE2BF  0x3F803F80u

__global__ __launch_bounds__(256, 1) void attn_kernel(
    const __nv_bfloat16* __restrict__ gq, const __nv_bfloat16* __restrict__ gk,
    const __nv_bfloat16* __restrict__ gv, __nv_bfloat16* __restrict__ gatt)
{
    extern __shared__ char sm[];
    const uint32_t smb = smem_u32(sm);

    const int tid  = threadIdx.x;
    const int lane = tid & 31;
    const int warp = tid >> 5;
    const int wm   = warp >> 1;        // 0..3 -> rows 32*wm
    const int wn   = warp & 1;         // key half for S; V-col half for PV

    const int b  = blockIdx.y;
    const int qt = blockIdx.x;

    const __nv_bfloat16* qb = gq + ((size_t)b * NTOK + qt * 128) * DD;
    const __nv_bfloat16* kb = gk + (size_t)b * NTOK * DD;
    const __nv_bfloat16* vb = gv + (size_t)b * NTOK * CC;

    auto sK_u = [&](int s) { return smb + AT_SK + s * A_KB; };
    auto sV_u = [&](int s) { return smb + AT_SV + s * A_VB; };
    auto sP_u = [&](int p) { return smb + AT_SP + p * PBUF; };

    auto load_tile = [&](int t, int s) {
        {
            int r = tid >> 2, c = tid & 3;
            cp_async16(sK_u(s) + r * (KSTRIDE * 2) + c * 16,
                       kb + ((size_t)t * 64 + r) * DD + c * 8);
        }
        #pragma unroll
        for (int i = 0; i < 8; i++) {
            int idx = tid + i * 256;
            int vr = idx >> 5, vc = idx & 31;
            cp_async16(sV_u(s) + vr * (VSTRIDE * 2) + vc * 16,
                       vb + ((size_t)t * 64 + vr) * CC + vc * 8);
        }
    };

    // stage Q (128x32 bf16)
    #pragma unroll
    for (int i = 0; i < 2; i++) {
        int idx = tid + i * 256;
        int r = idx >> 2, c = idx & 3;
        *(uint4*)(sm + AT_SQ + r * (KSTRIDE * 2) + c * 16) =
            *(const uint4*)(qb + (size_t)r * DD + c * 8);
    }
    load_tile(0, 0); cp_async_commit();
    load_tile(1, 1); cp_async_commit();
    __syncthreads();

    // Q fragments: [m-block][kbk][4]
    uint32_t qA[2][2][4];
    #pragma unroll
    for (int m = 0; m < 2; m++) {
        uint32_t base = smb + AT_SQ + (32 * wm + 16 * m + (lane & 15)) * (KSTRIDE * 2)
                        + ((lane >> 4) & 1) * 16;
        ldsm_x4(qA[m][0][0], qA[m][0][1], qA[m][0][2], qA[m][0][3], base);
        ldsm_x4(qA[m][1][0], qA[m][1][1], qA[m][1][2], qA[m][1][3], base + 32);
    }

    float acc[2][16][4];
    #pragma unroll
    for (int m = 0; m < 2; m++)
        #pragma unroll
        for (int j = 0; j < 16; j++)
            #pragma unroll
            for (int q4 = 0; q4 < 4; q4++) acc[m][j][q4] = 0.0f;
    float acc1[2][4];
    #pragma unroll
    for (int m = 0; m < 2; m++)
        #pragma unroll
        for (int q4 = 0; q4 < 4; q4++) acc1[m][q4] = 0.0f;

    const int krow4  = ((lane >> 4) & 1) * 8 + (lane & 7);
    const int kcolb4 = ((lane >> 3) & 1) * 16;
    const int vrow4  = (lane & 7) + ((lane >> 3) & 1) * 8;
    const int vcolb4 = ((lane >> 4) & 1) * 16;

    for (int kt = 0; kt < 64; kt++) {
        cp_async_wait1();          // tile kt resident
        __syncthreads();           // all warps past PV(kt-1); V(kt-2) slot free
        if (kt + 2 < 64) load_tile(kt + 2, (kt + 2) & 3);
        cp_async_commit();

        // ---- S = Q @ K^T for this warp's 32-key half, both m-blocks ----
        const uint32_t sKb = sK_u(kt & 3);
        float sfrag[2][4][4];
        #pragma unroll
        for (int m = 0; m < 2; m++)
            #pragma unroll
            for (int nt = 0; nt < 4; nt++)
                #pragma unroll
                for (int q4 = 0; q4 < 4; q4++) sfrag[m][nt][q4] = 0.0f;
        #pragma unroll
        for (int kbk = 0; kbk < 2; kbk++) {
            #pragma unroll
            for (int nt2 = 0; nt2 < 2; nt2++) {
                uint32_t b0, b1, b2, b3;
                ldsm_x4(b0, b1, b2, b3,
                        sKb + (wn * 32 + nt2 * 16 + krow4) * (KSTRIDE * 2) + kbk * 32 + kcolb4);
                #pragma unroll
                for (int m = 0; m < 2; m++) {
                    mma_bf16(sfrag[m][2 * nt2],     qA[m][kbk][0], qA[m][kbk][1], qA[m][kbk][2], qA[m][kbk][3], b0, b1);
                    mma_bf16(sfrag[m][2 * nt2 + 1], qA[m][kbk][0], qA[m][kbk][1], qA[m][kbk][2], qA[m][kbk][3], b2, b3);
                }
            }
        }

        // ---- P = exp2(S) -> smem P[kt&1] ----
        const uint32_t sPb = sP_u(kt & 1);
        #pragma unroll
        for (int m = 0; m < 2; m++) {
            uint32_t pbase = sPb + (32 * wm + 16 * m + (lane >> 2)) * (PSTRIDE * 2)
                             + (wn * 32 + (lane & 3) * 2) * 2;
            #pragma unroll
            for (int nt = 0; nt < 4; nt++) {
                uint32_t pb_lo = pack_bf16(ex2_fast(sfrag[m][nt][0]), ex2_fast(sfrag[m][nt][1]));
                uint32_t pb_hi = pack_bf16(ex2_fast(sfrag[m][nt][2]), ex2_fast(sfrag[m][nt][3]));
                uint32_t a0 = pbase + nt * 16;
                asm volatile("st.shared.b32 [%0], %1;" :: "r"(a0), "r"(pb_lo) : "memory");
                asm volatile("st.shared.b32 [%0], %1;" :: "r"(a0 + 8 * (PSTRIDE * 2)), "r"(pb_hi) : "memory");
            }
        }
        asm volatile("bar.sync %0, %1;" :: "r"(wm + 1), "r"(64) : "memory");

        // ---- O += P @ V: V frags shared across both m-blocks ----
        const uint32_t sVb = sV_u(kt & 3);
        #pragma unroll
        for (int kb2 = 0; kb2 < 4; kb2++) {
            uint32_t a[2][4];
            #pragma unroll
            for (int m = 0; m < 2; m++) {
                ldsm_x4(a[m][0], a[m][1], a[m][2], a[m][3],
                        sPb + (32 * wm + 16 * m + (lane & 15)) * (PSTRIDE * 2)
                        + kb2 * 32 + ((lane >> 4) & 1) * 16);
                mma_bf16(acc1[m], a[m][0], a[m][1], a[m][2], a[m][3], ONE2BF, ONE2BF);
            }
            #pragma unroll
            for (int j2 = 0; j2 < 8; j2++) {
                uint32_t b0, b1, b2, b3;
                ldsm_x4_trans(b0, b1, b2, b3,
                              sVb + (kb2 * 16 + vrow4) * (VSTRIDE * 2) + wn * 256 + j2 * 32 + vcolb4);
                #pragma unroll
                for (int m = 0; m < 2; m++) {
                    mma_bf16(acc[m][2 * j2],     a[m][0], a[m][1], a[m][2], a[m][3], b0, b1);
                    mma_bf16(acc[m][2 * j2 + 1], a[m][0], a[m][1], a[m][2], a[m][3], b2, b3);
                }
            }
        }
    }

    // epilogue
    __nv_bfloat16* ob = gatt + ((size_t)b * NTOK + qt * 128) * CC;
    #pragma unroll
    for (int m = 0; m < 2; m++) {
        float inv0 = 1.0f / acc1[m][0];
        float inv1 = 1.0f / acc1[m][2];
        int row0 = 32 * wm + 16 * m + (lane >> 2);
        int colb = wn * 128 + (lane & 3) * 2;
        #pragma unroll
        for (int j = 0; j < 16; j++) {
            int col = colb + j * 8;
            *(uint32_t*)&ob[(size_t)row0 * CC + col]       = pack_bf16(acc[m][j][0] * inv0, acc[m][j][1] * inv0);
            *(uint32_t*)&ob[(size_t)(row0 + 8) * CC + col] = pack_bf16(acc[m][j][2] * inv1, acc[m][j][3] * inv1);
        }
    }
}

// ---------------------------------------------------------------------------
extern "C" void kernel_launch(void* const* d_in, const int* in_sizes, int n_in,
                              void* d_out, int out_size)
{
    const float* x  = (const float*)d_in[0];
    const float* wq = (const float*)d_in[1];
    const float* bq = (const float*)d_in[2];
    const float* wk = (const float*)d_in[3];
    const float* bk = (const float*)d_in[4];
    const float* wv = (const float*)d_in[5];
    const float* bv = (const float*)d_in[6];
    const float* wo = (const float*)d_in[7];
    const float* bo = (const float*)d_in[8];
    float* out = (float*)d_out;

    __nv_bfloat16 *xb, *q, *k, *v, *att, *wqkb, *wvb, *wob;
    float* bqk;
    cudaGetSymbolAddress((void**)&xb,   g_xb);
    cudaGetSymbolAddress((void**)&q,    g_q);
    cudaGetSymbolAddress((void**)&k,    g_k);
    cudaGetSymbolAddress((void**)&v,    g_v);
    cudaGetSymbolAddress((void**)&att,  g_att);
    cudaGetSymbolAddress((void**)&wqkb, g_wqkb);
    cudaGetSymbolAddress((void**)&wvb,  g_wvb);
    cudaGetSymbolAddress((void**)&wob,  g_wob);
    cudaGetSymbolAddress((void**)&bqk,  g_bqk);

    dim3 blk(256);
    const float qscale = 1.4426950408889634f / 5.656854249492380f;  // log2(e)/sqrt(32)

    convert_all_kernel<<<MM * CC / 4 / 256, blk>>>((const float4*)x, wq, bq, wk, bk, wv, wo, qscale);

    const int smem64  = 4 * GEMM_A_STAGE + 4 * 32 * (64 + 8) * 2;    // 59392
    const int smem128 = 4 * GEMM_A_STAGE + 4 * 32 * (128 + 8) * 2;   // 75776
    cudaFuncSetAttribute(tc_gemm_kernel<64, 2>,  cudaFuncAttributeMaxDynamicSharedMemorySize, smem64);
    cudaFuncSetAttribute(tc_gemm_kernel<128, 0>, cudaFuncAttributeMaxDynamicSharedMemorySize, smem128);
    cudaFuncSetAttribute(tc_gemm_kernel<128, 1>, cudaFuncAttributeMaxDynamicSharedMemorySize, smem128);

    // fused Q|K projection, then V projection
    tc_gemm_kernel<64, 2><<<dim3(1, MM / 128), blk, smem64>>>(xb, wqkb, bqk, nullptr, q, k, 64);
    tc_gemm_kernel<128, 0><<<dim3(2, MM / 128), blk, smem128>>>(xb, wvb, bv, nullptr, v, nullptr, CC);

    // attention (256 threads, 128 queries/CTA, 32-row warp tiles)
    cudaFuncSetAttribute(attn_kernel, cudaFuncAttributeMaxDynamicSharedMemorySize, AT_TOT);
    attn_kernel<<<dim3(NTOK / 128, BB), blk, AT_TOT>>>(q, k, v, att);

    // output projection + bias + residual
    tc_gemm_kernel<128, 1><<<dim3(2, MM / 128), blk, smem128>>>(att, wob, bo, x, out, nullptr, CC);
}

// round 10
// speedup vs baseline: 7.6814x; 1.0292x over previous
#include <cuda_runtime.h>
#include <cuda_bf16.h>
#include <math.h>
#include <stdint.h>

#define BB   4
#define NTOK 4096
#define CC   256
#define DD   32
#define MM   (BB * NTOK)   // 16384

// Scratch (allocation-free per harness rules)
__device__ __nv_bfloat16 g_xb[MM * CC];
__device__ __nv_bfloat16 g_q[MM * DD];
__device__ __nv_bfloat16 g_k[MM * DD];
__device__ __nv_bfloat16 g_v[MM * CC];
__device__ __nv_bfloat16 g_att[MM * CC];
__device__ __nv_bfloat16 g_wqkb[CC * 64];   // cols 0-31 wq*qscale, 32-63 wk
__device__ __nv_bfloat16 g_wvb[CC * CC];
__device__ __nv_bfloat16 g_wob[CC * CC];
__device__ float         g_bqk[64];

// ---------------------------------------------------------------------------
// PTX helpers
// ---------------------------------------------------------------------------
__device__ __forceinline__ uint32_t smem_u32(const void* p) {
    return (uint32_t)__cvta_generic_to_shared(p);
}
__device__ __forceinline__ void ldsm_x4(uint32_t& r0, uint32_t& r1, uint32_t& r2, uint32_t& r3, uint32_t addr) {
    asm volatile("ldmatrix.sync.aligned.m8n8.x4.shared.b16 {%0,%1,%2,%3}, [%4];\n"
                 : "=r"(r0), "=r"(r1), "=r"(r2), "=r"(r3) : "r"(addr));
}
__device__ __forceinline__ void ldsm_x4_trans(uint32_t& r0, uint32_t& r1, uint32_t& r2, uint32_t& r3, uint32_t addr) {
    asm volatile("ldmatrix.sync.aligned.m8n8.x4.trans.shared.b16 {%0,%1,%2,%3}, [%4];\n"
                 : "=r"(r0), "=r"(r1), "=r"(r2), "=r"(r3) : "r"(addr));
}
__device__ __forceinline__ void mma_bf16(float* c, uint32_t a0, uint32_t a1, uint32_t a2, uint32_t a3,
                                         uint32_t b0, uint32_t b1) {
    asm volatile(
        "mma.sync.aligned.m16n8k16.row.col.f32.bf16.bf16.f32 "
        "{%0,%1,%2,%3}, {%4,%5,%6,%7}, {%8,%9}, {%0,%1,%2,%3};\n"
        : "+f"(c[0]), "+f"(c[1]), "+f"(c[2]), "+f"(c[3])
        : "r"(a0), "r"(a1), "r"(a2), "r"(a3), "r"(b0), "r"(b1));
}
__device__ __forceinline__ void cp_async16(uint32_t smem_dst, const void* gsrc) {
    asm volatile("cp.async.cg.shared.global [%0], [%1], 16;\n" :: "r"(smem_dst), "l"(gsrc));
}
__device__ __forceinline__ void cp_async_commit() { asm volatile("cp.async.commit_group;\n"); }
__device__ __forceinline__ void cp_async_wait1()  { asm volatile("cp.async.wait_group 1;\n"); }
__device__ __forceinline__ void cp_async_wait2()  { asm volatile("cp.async.wait_group 2;\n"); }

__device__ __forceinline__ uint32_t pack_bf16(float lo, float hi) {
    uint32_t r;
    asm("cvt.rn.bf16x2.f32 %0, %1, %2;" : "=r"(r) : "f"(hi), "f"(lo));
    return r;
}
__device__ __forceinline__ float ex2_fast(float x) {
    float y;
    asm("ex2.approx.ftz.f32 %0, %1;" : "=f"(y) : "f"(x));
    return y;
}

// ---------------------------------------------------------------------------
// merged fp32 -> bf16 conversion (x + all weights)
// ---------------------------------------------------------------------------
__global__ __launch_bounds__(256) void convert_all_kernel(
    const float4* __restrict__ x,
    const float* __restrict__ wq, const float* __restrict__ bq,
    const float* __restrict__ wk, const float* __restrict__ bk,
    const float* __restrict__ wv, const float* __restrict__ wo, float qscale)
{
    int i = blockIdx.x * 256 + threadIdx.x;
    float4 v = x[i];
    ((uint2*)g_xb)[i] = make_uint2(pack_bf16(v.x, v.y), pack_bf16(v.z, v.w));

    if (i < CC * CC) {
        g_wvb[i] = __float2bfloat16(wv[i]);
        g_wob[i] = __float2bfloat16(wo[i]);
    }
    if (i < CC * 64) {
        int r = i >> 6, c = i & 63;
        g_wqkb[i] = (c < 32) ? __float2bfloat16(wq[r * DD + c] * qscale)
                             : __float2bfloat16(wk[r * DD + c - 32]);
    }
    if (i < 64) g_bqk[i] = (i < 32) ? bq[i] * qscale : bk[i - 32];
}

// ---------------------------------------------------------------------------
// bf16 tensor-core GEMM, 4-stage cp.async pipeline (dynamic smem).
// MODE: 0 = bf16 out, 1 = fp32 out + resid, 2 = split Q/K bf16 out.
// ---------------------------------------------------------------------------
#define GXS 40   // A tile row stride (bf16)
#define GEMM_A_STAGE (128 * GXS * 2)   // 10240 B

template <int CTA_N, int MODE>
__global__ __launch_bounds__(256, 2) void tc_gemm_kernel(
    const __nv_bfloat16* __restrict__ A, const __nv_bfloat16* __restrict__ W,
    const float* __restrict__ bias, const float* __restrict__ resid,
    void* __restrict__ Yv, void* __restrict__ Y2, int N)
{
    constexpr int WS = CTA_N + 8;
    constexpr int NW = CTA_N / 8;
    constexpr int MW = 2;
    constexpr int NB = (CTA_N == 128) ? 8 : 4;
    constexpr int W_STAGE = 32 * WS * 2;

    extern __shared__ char gsm[];
    const uint32_t base = smem_u32(gsm);

    const int tid  = threadIdx.x;
    const int lane = tid & 31;
    const int warp = tid >> 5;
    const int wm   = warp >> 1;
    const int wn   = warp & 1;
    const int row0 = blockIdx.y * 128;
    const int n0   = blockIdx.x * CTA_N;

    auto sA_u = [&](int s) { return base + s * GEMM_A_STAGE; };
    auto sW_u = [&](int s) { return base + 4 * GEMM_A_STAGE + s * W_STAGE; };

    auto load_chunk = [&](int buf, int k0) {
        #pragma unroll
        for (int i = 0; i < 2; i++) {
            int idx = tid + i * 256;
            int r = idx >> 2, c = idx & 3;
            cp_async16(sA_u(buf) + r * (GXS * 2) + c * 16,
                       A + (size_t)(row0 + r) * CC + k0 + c * 8);
        }
        #pragma unroll
        for (int i = 0; i < (32 * NW + 255) / 256; i++) {
            int idx = tid + i * 256;
            int r = idx / NW, c = idx % NW;
            cp_async16(sW_u(buf) + r * (WS * 2) + c * 16,
                       W + (size_t)(k0 + r) * N + n0 + c * 8);
        }
        cp_async_commit();
    };

    load_chunk(0, 0);
    load_chunk(1, 32);
    load_chunk(2, 64);

    float acc[MW][NB][4];
    #pragma unroll
    for (int m = 0; m < MW; m++)
        #pragma unroll
        for (int nb = 0; nb < NB; nb++)
            #pragma unroll
            for (int q = 0; q < 4; q++) acc[m][nb][q] = 0.0f;

    const int arow = (lane & 15);
    const int acolb = ((lane >> 4) & 1) * 16;
    const int brow = (lane & 7) + ((lane >> 3) & 1) * 8;
    const int bcolb = ((lane >> 4) & 1) * 16;

    for (int ch = 0; ch < 8; ch++) {
        cp_async_wait2();
        __syncthreads();
        if (ch + 3 < 8) load_chunk((ch + 3) & 3, (ch + 3) * 32);
        else cp_async_commit();

        const uint32_t sAb = sA_u(ch & 3);
        const uint32_t sWb = sW_u(ch & 3);

        #pragma unroll
        for (int kk = 0; kk < 2; kk++) {
            uint32_t a[MW][4];
            #pragma unroll
            for (int m = 0; m < MW; m++)
                ldsm_x4(a[m][0], a[m][1], a[m][2], a[m][3],
                        sAb + (wm * (MW * 16) + m * 16 + arow) * (GXS * 2) + kk * 32 + acolb);
            #pragma unroll
            for (int nb2 = 0; nb2 < NB / 2; nb2++) {
                uint32_t b0, b1, b2, b3;
                ldsm_x4_trans(b0, b1, b2, b3,
                              sWb + (kk * 16 + brow) * (WS * 2) + (wn * (NB * 8) + nb2 * 16) * 2 + bcolb);
                #pragma unroll
                for (int m = 0; m < MW; m++) {
                    mma_bf16(acc[m][2 * nb2],     a[m][0], a[m][1], a[m][2], a[m][3], b0, b1);
                    mma_bf16(acc[m][2 * nb2 + 1], a[m][0], a[m][1], a[m][2], a[m][3], b2, b3);
                }
            }
        }
    }

    #pragma unroll
    for (int m = 0; m < MW; m++) {
        int r0 = row0 + wm * (MW * 16) + m * 16 + (lane >> 2);
        #pragma unroll
        for (int nb = 0; nb < NB; nb++) {
            int col = n0 + wn * (NB * 8) + nb * 8 + (lane & 3) * 2;
            #pragma unroll
            for (int h = 0; h < 2; h++) {
                int r = r0 + h * 8;
                float c0 = acc[m][nb][2 * h]     + bias[col];
                float c1 = acc[m][nb][2 * h + 1] + bias[col + 1];
                if (MODE == 1) {
                    float2 rr = *(const float2*)&resid[(size_t)r * N + col];
                    *(float2*)&((float*)Yv)[(size_t)r * N + col] = make_float2(c0 + rr.x, c1 + rr.y);
                } else if (MODE == 0) {
                    *(uint32_t*)&((__nv_bfloat16*)Yv)[(size_t)r * N + col] = pack_bf16(c0, c1);
                } else {
                    if (col < 32)
                        *(uint32_t*)&((__nv_bfloat16*)Yv)[(size_t)r * DD + col] = pack_bf16(c0, c1);
                    else
                        *(uint32_t*)&((__nv_bfloat16*)Y2)[(size_t)r * DD + col - 32] = pack_bf16(c0, c1);
                }
            }
        }
    }
}

// ---------------------------------------------------------------------------
// Flash attention: 256 threads, 8 warps (4 wm x 2 wn), 32-row warp tiles.
// PV(kt-1) MMAs interleaved with exp(kt) so the tensor pipe stays fed
// through the softmax window. 4-buffered K/V, double-buffered P.
// Row sums via ones-MMA.
// ---------------------------------------------------------------------------
#define KSTRIDE 40    // 80 B
#define VSTRIDE 264   // 528 B
#define A_KB    (64 * KSTRIDE * 2)    // 5120
#define A_VB    (64 * VSTRIDE * 2)    // 33792
#define PSTRIDE 72                    // 144 B
#define PBUF    (128 * PSTRIDE * 2)   // 18432
#define AT_SQ   0
#define AT_SK   (128 * KSTRIDE * 2)                // 10240
#define AT_SV   (AT_SK + 4 * A_KB)                 // 30720
#define AT_SP   (AT_SV + 4 * A_VB)                 // 165888
#define AT_TOT  (AT_SP + 2 * PBUF)                 // 202752
#define ONE2BF  0x3F803F80u

__global__ __launch_bounds__(256, 1) void attn_kernel(
    const __nv_bfloat16* __restrict__ gq, const __nv_bfloat16* __restrict__ gk,
    const __nv_bfloat16* __restrict__ gv, __nv_bfloat16* __restrict__ gatt)
{
    extern __shared__ char sm[];
    const uint32_t smb = smem_u32(sm);

    const int tid  = threadIdx.x;
    const int lane = tid & 31;
    const int warp = tid >> 5;
    const int wm   = warp >> 1;        // 0..3 -> rows 32*wm
    const int wn   = warp & 1;         // key half for S; V-col half for PV

    const int b  = blockIdx.y;
    const int qt = blockIdx.x;

    const __nv_bfloat16* qb = gq + ((size_t)b * NTOK + qt * 128) * DD;
    const __nv_bfloat16* kb = gk + (size_t)b * NTOK * DD;
    const __nv_bfloat16* vb = gv + (size_t)b * NTOK * CC;

    auto sK_u = [&](int s) { return smb + AT_SK + s * A_KB; };
    auto sV_u = [&](int s) { return smb + AT_SV + s * A_VB; };
    auto sP_u = [&](int p) { return smb + AT_SP + p * PBUF; };

    auto load_tile = [&](int t, int s) {
        {
            int r = tid >> 2, c = tid & 3;
            cp_async16(sK_u(s) + r * (KSTRIDE * 2) + c * 16,
                       kb + ((size_t)t * 64 + r) * DD + c * 8);
        }
        #pragma unroll
        for (int i = 0; i < 8; i++) {
            int idx = tid + i * 256;
            int vr = idx >> 5, vc = idx & 31;
            cp_async16(sV_u(s) + vr * (VSTRIDE * 2) + vc * 16,
                       vb + ((size_t)t * 64 + vr) * CC + vc * 8);
        }
    };

    // stage Q (128x32 bf16)
    #pragma unroll
    for (int i = 0; i < 2; i++) {
        int idx = tid + i * 256;
        int r = idx >> 2, c = idx & 3;
        *(uint4*)(sm + AT_SQ + r * (KSTRIDE * 2) + c * 16) =
            *(const uint4*)(qb + (size_t)r * DD + c * 8);
    }
    load_tile(0, 0); cp_async_commit();
    load_tile(1, 1); cp_async_commit();
    __syncthreads();

    // Q fragments: [m-block][kbk][4]
    uint32_t qA[2][2][4];
    #pragma unroll
    for (int m = 0; m < 2; m++) {
        uint32_t base = smb + AT_SQ + (32 * wm + 16 * m + (lane & 15)) * (KSTRIDE * 2)
                        + ((lane >> 4) & 1) * 16;
        ldsm_x4(qA[m][0][0], qA[m][0][1], qA[m][0][2], qA[m][0][3], base);
        ldsm_x4(qA[m][1][0], qA[m][1][1], qA[m][1][2], qA[m][1][3], base + 32);
    }

    float acc[2][16][4];
    #pragma unroll
    for (int m = 0; m < 2; m++)
        #pragma unroll
        for (int j = 0; j < 16; j++)
            #pragma unroll
            for (int q4 = 0; q4 < 4; q4++) acc[m][j][q4] = 0.0f;
    float acc1[2][4];
    #pragma unroll
    for (int m = 0; m < 2; m++)
        #pragma unroll
        for (int q4 = 0; q4 < 4; q4++) acc1[m][q4] = 0.0f;

    const int krow4  = ((lane >> 4) & 1) * 8 + (lane & 7);
    const int kcolb4 = ((lane >> 3) & 1) * 16;
    const int vrow4  = (lane & 7) + ((lane >> 3) & 1) * 8;
    const int vcolb4 = ((lane >> 4) & 1) * 16;
    const uint32_t pwr_base = (32 * wm + (lane >> 2)) * (PSTRIDE * 2) + (wn * 32 + (lane & 3) * 2) * 2;
    const uint32_t prd_base = (32 * wm + (lane & 15)) * (PSTRIDE * 2) + ((lane >> 4) & 1) * 16;

    for (int kt = 0; kt < 64; kt++) {
        cp_async_wait1();          // tile kt resident
        __syncthreads();           // all warps past PV(kt-2); V slot free
        if (kt + 2 < 64) load_tile(kt + 2, (kt + 2) & 3);
        cp_async_commit();

        // ---- S = Q @ K^T for this warp's 32-key half, both m-blocks ----
        const uint32_t sKb = sK_u(kt & 3);
        float sfrag[2][4][4];
        #pragma unroll
        for (int m = 0; m < 2; m++)
            #pragma unroll
            for (int nt = 0; nt < 4; nt++)
                #pragma unroll
                for (int q4 = 0; q4 < 4; q4++) sfrag[m][nt][q4] = 0.0f;
        #pragma unroll
        for (int kbk = 0; kbk < 2; kbk++) {
            #pragma unroll
            for (int nt2 = 0; nt2 < 2; nt2++) {
                uint32_t b0, b1, b2, b3;
                ldsm_x4(b0, b1, b2, b3,
                        sKb + (wn * 32 + nt2 * 16 + krow4) * (KSTRIDE * 2) + kbk * 32 + kcolb4);
                #pragma unroll
                for (int m = 0; m < 2; m++) {
                    mma_bf16(sfrag[m][2 * nt2],     qA[m][kbk][0], qA[m][kbk][1], qA[m][kbk][2], qA[m][kbk][3], b0, b1);
                    mma_bf16(sfrag[m][2 * nt2 + 1], qA[m][kbk][0], qA[m][kbk][1], qA[m][kbk][2], qA[m][kbk][3], b2, b3);
                }
            }
        }

        // ---- interleaved: PV(kt-1) chunks fed to tensor pipe while MUFU
        //      computes exp(kt); both streams in one unrolled block ----
        const uint32_t sPprev = sP_u((kt + 1) & 1);       // P of kt-1
        const uint32_t sPcur  = sP_u(kt & 1);
        const uint32_t sVprev = sV_u((kt + 3) & 3);       // V of kt-1
        #pragma unroll
        for (int kb2 = 0; kb2 < 4; kb2++) {
            // PV(kt-1) chunk kb2
            if (kt > 0) {
                uint32_t a[2][4];
                #pragma unroll
                for (int m = 0; m < 2; m++) {
                    ldsm_x4(a[m][0], a[m][1], a[m][2], a[m][3],
                            sPprev + prd_base + 16 * m * (PSTRIDE * 2) + kb2 * 32);
                    mma_bf16(acc1[m], a[m][0], a[m][1], a[m][2], a[m][3], ONE2BF, ONE2BF);
                }
                #pragma unroll
                for (int j2 = 0; j2 < 8; j2++) {
                    uint32_t b0, b1, b2, b3;
                    ldsm_x4_trans(b0, b1, b2, b3,
                                  sVprev + (kb2 * 16 + vrow4) * (VSTRIDE * 2) + wn * 256 + j2 * 32 + vcolb4);
                    #pragma unroll
                    for (int m = 0; m < 2; m++) {
                        mma_bf16(acc[m][2 * j2],     a[m][0], a[m][1], a[m][2], a[m][3], b0, b1);
                        mma_bf16(acc[m][2 * j2 + 1], a[m][0], a[m][1], a[m][2], a[m][3], b2, b3);
                    }
                }
            }
            // exp chunk nt = kb2 of S(kt): 8 EX2 + 4 cvt + 4 STS
            #pragma unroll
            for (int m = 0; m < 2; m++) {
                uint32_t pb_lo = pack_bf16(ex2_fast(sfrag[m][kb2][0]), ex2_fast(sfrag[m][kb2][1]));
                uint32_t pb_hi = pack_bf16(ex2_fast(sfrag[m][kb2][2]), ex2_fast(sfrag[m][kb2][3]));
                uint32_t a0 = sPcur + pwr_base + 16 * m * (PSTRIDE * 2) + kb2 * 16;
                asm volatile("st.shared.b32 [%0], %1;" :: "r"(a0), "r"(pb_lo) : "memory");
                asm volatile("st.shared.b32 [%0], %1;" :: "r"(a0 + 8 * (PSTRIDE * 2)), "r"(pb_hi) : "memory");
            }
        }
        asm volatile("bar.sync %0, %1;" :: "r"(wm + 1), "r"(64) : "memory");
    }

    // epilogue: PV(63)
    {
        const uint32_t sPprev = sP_u(63 & 1);
        const uint32_t sVprev = sV_u(63 & 3);
        #pragma unroll
        for (int kb2 = 0; kb2 < 4; kb2++) {
            uint32_t a[2][4];
            #pragma unroll
            for (int m = 0; m < 2; m++) {
                ldsm_x4(a[m][0], a[m][1], a[m][2], a[m][3],
                        sPprev + prd_base + 16 * m * (PSTRIDE * 2) + kb2 * 32);
                mma_bf16(acc1[m], a[m][0], a[m][1], a[m][2], a[m][3], ONE2BF, ONE2BF);
            }
            #pragma unroll
            for (int j2 = 0; j2 < 8; j2++) {
                uint32_t b0, b1, b2, b3;
                ldsm_x4_trans(b0, b1, b2, b3,
                              sVprev + (kb2 * 16 + vrow4) * (VSTRIDE * 2) + wn * 256 + j2 * 32 + vcolb4);
                #pragma unroll
                for (int m = 0; m < 2; m++) {
                    mma_bf16(acc[m][2 * j2],     a[m][0], a[m][1], a[m][2], a[m][3], b0, b1);
                    mma_bf16(acc[m][2 * j2 + 1], a[m][0], a[m][1], a[m][2], a[m][3], b2, b3);
                }
            }
        }
    }

    // epilogue: normalize + store
    __nv_bfloat16* ob = gatt + ((size_t)b * NTOK + qt * 128) * CC;
    #pragma unroll
    for (int m = 0; m < 2; m++) {
        float inv0 = 1.0f / acc1[m][0];
        float inv1 = 1.0f / acc1[m][2];
        int row0 = 32 * wm + 16 * m + (lane >> 2);
        int colb = wn * 128 + (lane & 3) * 2;
        #pragma unroll
        for (int j = 0; j < 16; j++) {
            int col = colb + j * 8;
            *(uint32_t*)&ob[(size_t)row0 * CC + col]       = pack_bf16(acc[m][j][0] * inv0, acc[m][j][1] * inv0);
            *(uint32_t*)&ob[(size_t)(row0 + 8) * CC + col] = pack_bf16(acc[m][j][2] * inv1, acc[m][j][3] * inv1);
        }
    }
}

// ---------------------------------------------------------------------------
extern "C" void kernel_launch(void* const* d_in, const int* in_sizes, int n_in,
                              void* d_out, int out_size)
{
    const float* x  = (const float*)d_in[0];
    const float* wq = (const float*)d_in[1];
    const float* bq = (const float*)d_in[2];
    const float* wk = (const float*)d_in[3];
    const float* bk = (const float*)d_in[4];
    const float* wv = (const float*)d_in[5];
    const float* bv = (const float*)d_in[6];
    const float* wo = (const float*)d_in[7];
    const float* bo = (const float*)d_in[8];
    float* out = (float*)d_out;

    __nv_bfloat16 *xb, *q, *k, *v, *att, *wqkb, *wvb, *wob;
    float* bqk;
    cudaGetSymbolAddress((void**)&xb,   g_xb);
    cudaGetSymbolAddress((void**)&q,    g_q);
    cudaGetSymbolAddress((void**)&k,    g_k);
    cudaGetSymbolAddress((void**)&v,    g_v);
    cudaGetSymbolAddress((void**)&att,  g_att);
    cudaGetSymbolAddress((void**)&wqkb, g_wqkb);
    cudaGetSymbolAddress((void**)&wvb,  g_wvb);
    cudaGetSymbolAddress((void**)&wob,  g_wob);
    cudaGetSymbolAddress((void**)&bqk,  g_bqk);

    dim3 blk(256);
    const float qscale = 1.4426950408889634f / 5.656854249492380f;  // log2(e)/sqrt(32)

    convert_all_kernel<<<MM * CC / 4 / 256, blk>>>((const float4*)x, wq, bq, wk, bk, wv, wo, qscale);

    const int smem64  = 4 * GEMM_A_STAGE + 4 * 32 * (64 + 8) * 2;    // 59392
    const int smem128 = 4 * GEMM_A_STAGE + 4 * 32 * (128 + 8) * 2;   // 75776
    cudaFuncSetAttribute(tc_gemm_kernel<64, 2>,  cudaFuncAttributeMaxDynamicSharedMemorySize, smem64);
    cudaFuncSetAttribute(tc_gemm_kernel<128, 0>, cudaFuncAttributeMaxDynamicSharedMemorySize, smem128);
    cudaFuncSetAttribute(tc_gemm_kernel<128, 1>, cudaFuncAttributeMaxDynamicSharedMemorySize, smem128);

    // fused Q|K projection, then V projection
    tc_gemm_kernel<64, 2><<<dim3(1, MM / 128), blk, smem64>>>(xb, wqkb, bqk, nullptr, q, k, 64);
    tc_gemm_kernel<128, 0><<<dim3(2, MM / 128), blk, smem128>>>(xb, wvb, bv, nullptr, v, nullptr, CC);

    // attention (256 threads, 128 queries/CTA, 32-row warp tiles, interleaved)
    cudaFuncSetAttribute(attn_kernel, cudaFuncAttributeMaxDynamicSharedMemorySize, AT_TOT);
    attn_kernel<<<dim3(NTOK / 128, BB), blk, AT_TOT>>>(q, k, v, att);

    // output projection + bias + residual
    tc_gemm_kernel<128, 1><<<dim3(2, MM / 128), blk, smem128>>>(att, wob, bo, x, out, nullptr, CC);
}